// round 12
// baseline (speedup 1.0000x reference)
#include <cuda_runtime.h>
#include <cuda_bf16.h>
#include <stdint.h>

typedef unsigned u32; typedef unsigned long long u64;

#define K_CODES 1024
#define D_DIM   256
#define N_TOK   32768
#define Q_ELEMS (8u*256u*4096u)
#define TAU     0.75f
#define TAU2    0.003f

#define XPITCH  264        /* x smem row pitch in bf16 elements (528 B) */
#define BPITCH  144        /* e tile row pitch in bytes (128 data + 16) */
#define SM_BT   18432      /* one 128-code x 64-d bf16 tile             */

/* main kernel smem map */
#define SM_XH   0
#define SM_B    67584
#define SM_TOTAL (67584 + 2 * SM_BT)          /* 104448 */

/* tensor-rescue smem map: 64 tokens/CTA */
#define RS_XH   0
#define RS_XL   33792
#define RS_B    67584
#define RS_TOTAL (67584 + 4 * SM_BT)          /* 141312 */

// ---------------- device scratch ----------------
__device__ __align__(16) __nv_bfloat16 g_Ebf[2][K_CODES][D_DIM];  // hi/lo of -2*embed
__device__ float g_e2[K_CODES];
__device__ int   g_idx[N_TOK];
__device__ float g_batch_cs[K_CODES];
__device__ float g_dw[K_CODES * D_DIM];
__device__ float g_partials[32 * 128];
__device__ int   g_flag_cnt;
__device__ int   g_flag_tok[N_TOK];
__device__ int   g_flag2_cnt;
__device__ int   g_flag2_tok[N_TOK];
__device__ u64   g_best2[N_TOK];

// ---------------- helpers ----------------
__device__ __forceinline__ u32 smem_u32(const void* p) {
    u32 a; asm("{ .reg .u64 t; cvta.to.shared.u64 t, %1; cvt.u32.u64 %0, t; }" : "=r"(a) : "l"(p)); return a;
}
__device__ __forceinline__ u32 fkey(float v) {
    u32 u = __float_as_uint(v); return (u & 0x80000000u) ? ~u : (u | 0x80000000u);
}
__device__ __forceinline__ float fkeyinv(u32 k) {
    u32 u = (k & 0x80000000u) ? (k & 0x7FFFFFFFu) : ~k; return __uint_as_float(u);
}
__device__ __forceinline__ void cpa16(u32 dst, const void* src) {
    asm volatile("cp.async.cg.shared.global [%0], [%1], 16;" :: "r"(dst), "l"(src));
}
#define CP_COMMIT() asm volatile("cp.async.commit_group;" ::: "memory")
#define CP_WAIT1()  asm volatile("cp.async.wait_group 1;" ::: "memory")
#define CP_WAIT0()  asm volatile("cp.async.wait_group 0;" ::: "memory")

__device__ __forceinline__ void ldm4(u32& r0, u32& r1, u32& r2, u32& r3, u32 a) {
    asm volatile("ldmatrix.sync.aligned.m8n8.x4.shared.b16 {%0,%1,%2,%3}, [%4];"
                 : "=r"(r0), "=r"(r1), "=r"(r2), "=r"(r3) : "r"(a));
}
__device__ __forceinline__ void mma16816(float* c, const u32* a, const u32* b) {
    asm volatile("mma.sync.aligned.m16n8k16.row.col.f32.bf16.bf16.f32 "
                 "{%0,%1,%2,%3}, {%4,%5,%6,%7}, {%8,%9}, {%0,%1,%2,%3};"
                 : "+f"(c[0]), "+f"(c[1]), "+f"(c[2]), "+f"(c[3])
                 : "r"(a[0]), "r"(a[1]), "r"(a[2]), "r"(a[3]), "r"(b[0]), "r"(b[1]));
}
__device__ __forceinline__ void track(u64& b1, u32& b2, u64 pk) {
    if (pk < b1) { b2 = min(b2, (u32)(b1 >> 32)); b1 = pk; }
    else         { b2 = min(b2, (u32)(pk >> 32)); }
}

// ---------------- prep: bf16 hi/lo of -2*embed + e2 ----------------
__global__ void k_esplit(const float* __restrict__ embed) {
    int k = blockIdx.x, d = threadIdx.x;
    float e = embed[k * D_DIM + d];
    float v = -2.0f * e;
    __nv_bfloat16 h = __float2bfloat16(v);
    g_Ebf[0][k][d] = h;
    g_Ebf[1][k][d] = __float2bfloat16(v - __bfloat162float(h));
    float s = e * e;
    #pragma unroll
    for (int o = 16; o; o >>= 1) s += __shfl_down_sync(0xffffffffu, s, o);
    __shared__ float ws[8];
    if ((d & 31) == 0) ws[d >> 5] = s;
    __syncthreads();
    if (d == 0) {
        float t = 0.f;
        #pragma unroll
        for (int i = 0; i < 8; i++) t += ws[i];
        g_e2[k] = t;
    }
}

// ---------------- level 1: single-pass xh*eh GEMM over all tokens ----------------
__global__ void __launch_bounds__(256, 1) k_argmin(const float* __restrict__ x) {
    extern __shared__ __align__(128) char smem[];
    u32 smb = smem_u32(smem);
    const int tid = threadIdx.x, l = tid & 31, wid = tid >> 5;
    const int wm = wid & 3, wn = wid >> 2;
    const int m0 = blockIdx.x * 128;
    const int b = m0 >> 12, s0 = m0 & 4095;

    __nv_bfloat16* xh = (__nv_bfloat16*)(smem + SM_XH);
    {   // fill x tile (hi only): [128 tok][256 d]
        int tok = tid & 127, dh = tid >> 7;
        const float* xp = x + (size_t)b * 1048576u + s0 + tok;
        #pragma unroll 4
        for (int i = 0; i < 128; i++) {
            int d = dh + 2 * i;
            xh[tok * XPITCH + d] = __float2bfloat16(xp[(size_t)d * 4096u]);
        }
    }

    auto prefetch = [&](int step) {
        int tile = step >> 2, chunk = step & 3;
        u32 dst = smb + SM_B + (u32)(step & 1) * SM_BT;
        const char* src0 = (const char*)&g_Ebf[0][tile * 128][0] + chunk * 128;
        #pragma unroll
        for (int i = 0; i < 4; i++) {
            int idx = tid + i * 256;
            int crow = idx >> 3, seg = idx & 7;
            cpa16(dst + crow * BPITCH + seg * 16, src0 + (size_t)crow * 512 + seg * 16);
        }
        CP_COMMIT();
    };

    float acc[2][8][4];
    u64 b1[4]; u32 b2[4];
    #pragma unroll
    for (int q = 0; q < 4; q++) { b1[q] = ~0ull; b2[q] = 0xFFFFFFFFu; }
    #pragma unroll
    for (int mt = 0; mt < 2; mt++)
        #pragma unroll
        for (int nt = 0; nt < 8; nt++)
            #pragma unroll
            for (int r = 0; r < 4; r++) acc[mt][nt][r] = 0.f;

    __syncthreads();
    prefetch(0);

    const u32 aoff = (u32)((l & 7) + ((l >> 3) & 1) * 8) * 528 + ((l >> 4) & 1) * 16;
    const u32 boff = (u32)((l & 7) + ((l >> 4) & 1) * 8) * BPITCH + ((l >> 3) & 1) * 16;

    for (int step = 0; step < 32; step++) {
        int tile = step >> 2, chunk = step & 3;
        if (step < 31) { prefetch(step + 1); CP_WAIT1(); } else { CP_WAIT0(); }
        __syncthreads();
        u32 Bb = smb + SM_B + (u32)(step & 1) * SM_BT;
        #pragma unroll
        for (int ks = 0; ks < 4; ks++) {
            u32 kbyte = (u32)chunk * 128 + ks * 32;
            u32 ah[2][4];
            #pragma unroll
            for (int mt = 0; mt < 2; mt++)
                ldm4(ah[mt][0], ah[mt][1], ah[mt][2], ah[mt][3],
                     smb + SM_XH + (u32)(wm * 32 + mt * 16) * 528 + kbyte + aoff);
            u32 bb[4][4];
            #pragma unroll
            for (int ng = 0; ng < 4; ng++)
                ldm4(bb[ng][0], bb[ng][1], bb[ng][2], bb[ng][3],
                     Bb + (u32)(wn * 64 + ng * 16) * BPITCH + ks * 32 + boff);
            #pragma unroll
            for (int mt = 0; mt < 2; mt++)
                #pragma unroll
                for (int ng = 0; ng < 4; ng++) {
                    mma16816(acc[mt][ng * 2],     ah[mt], &bb[ng][0]);
                    mma16816(acc[mt][ng * 2 + 1], ah[mt], &bb[ng][2]);
                }
        }
        if (chunk == 3) {
            float2 e2v[8];
            #pragma unroll
            for (int nt = 0; nt < 8; nt++)
                e2v[nt] = *(const float2*)(g_e2 + tile * 128 + wn * 64 + nt * 8 + 2 * (l & 3));
            #pragma unroll
            for (int mt = 0; mt < 2; mt++)
                #pragma unroll
                for (int nt = 0; nt < 8; nt++)
                    #pragma unroll
                    for (int r = 0; r < 4; r++) {
                        float v = acc[mt][nt][r] + ((r & 1) ? e2v[nt].y : e2v[nt].x);
                        u32 col = (u32)(tile * 128 + wn * 64 + nt * 8 + 2 * (l & 3) + (r & 1));
                        track(b1[mt * 2 + (r >> 1)], b2[mt * 2 + (r >> 1)],
                              ((u64)fkey(v) << 32) | col);
                        acc[mt][nt][r] = 0.f;
                    }
        }
        __syncthreads();
    }

    // merge lanes (l&3) sharing each row
    #pragma unroll
    for (int tr = 0; tr < 4; tr++)
        #pragma unroll
        for (int off = 1; off <= 2; off <<= 1) {
            u64 o1 = __shfl_xor_sync(0xffffffffu, b1[tr], off);
            u32 o2 = __shfl_xor_sync(0xffffffffu, b2[tr], off);
            u64 mx = (b1[tr] > o1) ? b1[tr] : o1;
            b1[tr] = (b1[tr] < o1) ? b1[tr] : o1;
            b2[tr] = min(min(b2[tr], o2), (u32)(mx >> 32));
        }
    u64* tab1 = (u64*)(smem + SM_B);
    u32* tab2 = (u32*)(smem + SM_B + 2048);
    if ((l & 3) == 0)
        #pragma unroll
        for (int tr = 0; tr < 4; tr++) {
            int row = wm * 32 + (tr >> 1) * 16 + (tr & 1) * 8 + (l >> 2);
            tab1[row * 2 + wn] = b1[tr];
            tab2[row * 2 + wn] = b2[tr];
        }
    __syncthreads();
    if (tid < 128) {
        u64 p = tab1[tid * 2], q = tab1[tid * 2 + 1];
        u64 best = p < q ? p : q, worse = p < q ? q : p;
        u32 sec = min(min(tab2[tid * 2], tab2[tid * 2 + 1]), (u32)(worse >> 32));
        int n = m0 + tid;
        g_idx[n] = (int)(best & 0xFFFFFFFFull);
        float margin = fkeyinv(sec) - fkeyinv((u32)(best >> 32));
        if (!(margin > TAU)) { int pp = atomicAdd(&g_flag_cnt, 1); g_flag_tok[pp] = n; }
    }
}

// ---------------- level 2: 3-pass tensor rescue, 64 flagged tokens / CTA ----------------
__global__ void __launch_bounds__(256, 1) k_rescue_t(const float* __restrict__ x) {
    extern __shared__ __align__(128) char smem[];
    u32 smb = smem_u32(smem);
    const int tid = threadIdx.x, l = tid & 31, wn = tid >> 5;   // 8 warps, 16 codes each
    int cnt = *((volatile int*)&g_flag_cnt);
    int G = (cnt + 63) >> 6;

    const u32 aoff = (u32)((l & 7) + ((l >> 3) & 1) * 8) * 528 + ((l >> 4) & 1) * 16;
    const u32 boff = (u32)((l & 7) + ((l >> 4) & 1) * 8) * BPITCH + ((l >> 3) & 1) * 16;
    __nv_bfloat16* xh = (__nv_bfloat16*)(smem + RS_XH);
    __nv_bfloat16* xl = (__nv_bfloat16*)(smem + RS_XL);

    for (int g = blockIdx.x; g < G; g += gridDim.x) {
        {   // gather 64 flagged tokens into smem hi/lo
            int slot = tid >> 2, seg = tid & 3;
            int li = g * 64 + slot;
            int n = g_flag_tok[li < cnt ? li : cnt - 1];
            int b = n >> 12, s = n & 4095;
            const float* xp = x + (size_t)b * 1048576u + s;
            #pragma unroll 4
            for (int i = 0; i < 64; i++) {
                int d = seg * 64 + i;
                float v = xp[(size_t)d * 4096u];
                __nv_bfloat16 h = __float2bfloat16(v);
                xh[slot * XPITCH + d] = h;
                xl[slot * XPITCH + d] = __float2bfloat16(v - __bfloat162float(h));
            }
        }

        auto prefetch = [&](int step) {
            int tile = step >> 2, chunk = step & 3;
            u32 dstb = smb + RS_B + (u32)(step & 1) * (2 * SM_BT);
            #pragma unroll
            for (int op = 0; op < 2; op++) {
                const char* src0 = (const char*)&g_Ebf[op][tile * 128][0] + chunk * 128;
                u32 dst = dstb + op * SM_BT;
                #pragma unroll
                for (int i = 0; i < 4; i++) {
                    int idx = tid + i * 256;
                    int crow = idx >> 3, seg = idx & 7;
                    cpa16(dst + crow * BPITCH + seg * 16, src0 + (size_t)crow * 512 + seg * 16);
                }
            }
            CP_COMMIT();
        };

        float acc[4][2][4];
        u64 b1[8]; u32 b2[8];
        #pragma unroll
        for (int q = 0; q < 8; q++) { b1[q] = ~0ull; b2[q] = 0xFFFFFFFFu; }
        #pragma unroll
        for (int mt = 0; mt < 4; mt++)
            #pragma unroll
            for (int nh = 0; nh < 2; nh++)
                #pragma unroll
                for (int r = 0; r < 4; r++) acc[mt][nh][r] = 0.f;

        __syncthreads();
        prefetch(0);

        for (int step = 0; step < 32; step++) {
            int tile = step >> 2, chunk = step & 3;
            if (step < 31) { prefetch(step + 1); CP_WAIT1(); } else { CP_WAIT0(); }
            __syncthreads();
            u32 Bb = smb + RS_B + (u32)(step & 1) * (2 * SM_BT);
            #pragma unroll
            for (int ks = 0; ks < 4; ks++) {
                u32 kbyte = (u32)chunk * 128 + ks * 32;
                u32 ah[4][4], al[4][4], bh[4], bl[4];
                #pragma unroll
                for (int mt = 0; mt < 4; mt++) {
                    u32 rowb = (u32)(mt * 16) * 528 + kbyte + aoff;
                    ldm4(ah[mt][0], ah[mt][1], ah[mt][2], ah[mt][3], smb + RS_XH + rowb);
                    ldm4(al[mt][0], al[mt][1], al[mt][2], al[mt][3], smb + RS_XL + rowb);
                }
                u32 brow = (u32)(wn * 16) * BPITCH + ks * 32 + boff;
                ldm4(bh[0], bh[1], bh[2], bh[3], Bb + brow);
                ldm4(bl[0], bl[1], bl[2], bl[3], Bb + SM_BT + brow);
                #pragma unroll
                for (int mt = 0; mt < 4; mt++) {
                    mma16816(acc[mt][0], ah[mt], &bh[0]);
                    mma16816(acc[mt][1], ah[mt], &bh[2]);
                    mma16816(acc[mt][0], ah[mt], &bl[0]);
                    mma16816(acc[mt][1], ah[mt], &bl[2]);
                    mma16816(acc[mt][0], al[mt], &bh[0]);
                    mma16816(acc[mt][1], al[mt], &bh[2]);
                }
            }
            if (chunk == 3) {
                float2 e2v[2];
                #pragma unroll
                for (int nh = 0; nh < 2; nh++)
                    e2v[nh] = *(const float2*)(g_e2 + tile * 128 + wn * 16 + nh * 8 + 2 * (l & 3));
                #pragma unroll
                for (int mt = 0; mt < 4; mt++)
                    #pragma unroll
                    for (int nh = 0; nh < 2; nh++)
                        #pragma unroll
                        for (int r = 0; r < 4; r++) {
                            float v = acc[mt][nh][r] + ((r & 1) ? e2v[nh].y : e2v[nh].x);
                            u32 col = (u32)(tile * 128 + wn * 16 + nh * 8 + 2 * (l & 3) + (r & 1));
                            track(b1[mt * 2 + (r >> 1)], b2[mt * 2 + (r >> 1)],
                                  ((u64)fkey(v) << 32) | col);
                            acc[mt][nh][r] = 0.f;
                        }
            }
            __syncthreads();
        }

        #pragma unroll
        for (int tr = 0; tr < 8; tr++)
            #pragma unroll
            for (int off = 1; off <= 2; off <<= 1) {
                u64 o1 = __shfl_xor_sync(0xffffffffu, b1[tr], off);
                u32 o2 = __shfl_xor_sync(0xffffffffu, b2[tr], off);
                u64 mx = (b1[tr] > o1) ? b1[tr] : o1;
                b1[tr] = (b1[tr] < o1) ? b1[tr] : o1;
                b2[tr] = min(min(b2[tr], o2), (u32)(mx >> 32));
            }
        u64* tab1 = (u64*)(smem + RS_B);
        u32* tab2 = (u32*)(smem + RS_B + 4096);
        if ((l & 3) == 0)
            #pragma unroll
            for (int tr = 0; tr < 8; tr++) {
                int row = (tr >> 1) * 16 + (tr & 1) * 8 + (l >> 2);
                tab1[row * 8 + wn] = b1[tr];
                tab2[row * 8 + wn] = b2[tr];
            }
        __syncthreads();
        if (tid < 64) {
            u64 best = ~0ull; u32 sec = 0xFFFFFFFFu;
            #pragma unroll
            for (int w = 0; w < 8; w++) {
                u64 p = tab1[tid * 8 + w];
                if (p < best) { sec = min(sec, (u32)(best >> 32)); best = p; }
                else          { sec = min(sec, (u32)(p >> 32)); }
                sec = min(sec, tab2[tid * 8 + w]);
            }
            int li = g * 64 + tid;
            if (li < cnt) {
                int n = g_flag_tok[li];
                float margin = fkeyinv(sec) - fkeyinv((u32)(best >> 32));
                if (margin > TAU2) g_idx[n] = (int)(best & 0xFFFFFFFFull);
                else {
                    int pp = atomicAdd(&g_flag2_cnt, 1);
                    g_flag2_tok[pp] = n;
                    g_best2[pp] = ~0ull;
                }
            }
        }
        __syncthreads();
    }
}

// ---------------- level 3: exact fp32, parallel over (token, 128-code chunk) ----------------
__global__ void __launch_bounds__(256) k_rescue_exact(const float* __restrict__ x,
                                                      const float* __restrict__ embed) {
    __shared__ float xs[256];
    __shared__ float part[256];
    __shared__ u64 red[128];
    int tid = threadIdx.x;
    int cnt = *((volatile int*)&g_flag2_cnt);
    int code = blockIdx.y * 128 + (tid & 127);
    int half = tid >> 7;
    for (int i = blockIdx.x; i < cnt; i += gridDim.x) {
        int n = g_flag2_tok[i];
        int b = n >> 12, s = n & 4095;
        xs[tid] = x[(size_t)b * 1048576u + (size_t)tid * 4096u + s];
        __syncthreads();
        const float4* e4 = (const float4*)(embed + code * 256) + half * 32;
        const float* xsp = xs + half * 128;
        float acc = 0.f;
        #pragma unroll 8
        for (int q = 0; q < 32; q++) {
            float4 ev = e4[q];
            acc = fmaf(ev.x, xsp[q*4+0], acc);
            acc = fmaf(ev.y, xsp[q*4+1], acc);
            acc = fmaf(ev.z, xsp[q*4+2], acc);
            acc = fmaf(ev.w, xsp[q*4+3], acc);
        }
        part[tid] = acc;
        __syncthreads();
        if (tid < 128) {
            float sc = g_e2[code] - 2.f * (part[tid] + part[tid + 128]);
            red[tid] = ((u64)fkey(sc) << 32) | (u32)code;
        }
        __syncthreads();
        for (int o = 64; o; o >>= 1) {
            if (tid < o) red[tid] = min(red[tid], red[tid + o]);
            __syncthreads();
        }
        if (tid == 0) atomicMin(&g_best2[i], red[0]);
        __syncthreads();
    }
}

__global__ void k_rescue_fin() {
    int cnt = *((volatile int*)&g_flag2_cnt);
    for (int i = threadIdx.x; i < cnt; i += blockDim.x)
        g_idx[g_flag2_tok[i]] = (int)(g_best2[i] & 0xFFFFFFFFull);
}

// ---------------- fused quantized write + loss + dw scatter + idx out ----------------
__global__ void k_quant_dw(const float* __restrict__ x,
                           const float* __restrict__ embed,
                           float* __restrict__ qout, float* __restrict__ idxf_out)
{
    int d0 = blockIdx.x << 3;
    int n  = (blockIdx.y << 8) + threadIdx.x;
    int b = n >> 12, s = n & 4095;
    size_t base = (size_t)b * 1048576u + s;
    int k = g_idx[n];
    float4 q0 = *(const float4*)(embed + k * D_DIM + d0);
    float4 q1 = *(const float4*)(embed + k * D_DIM + d0 + 4);
    if (blockIdx.x == 0) { idxf_out[n] = (float)k; atomicAdd(&g_batch_cs[k], 1.0f); }

    float xv[8], qv[8] = {q0.x, q0.y, q0.z, q0.w, q1.x, q1.y, q1.z, q1.w};
    #pragma unroll
    for (int i = 0; i < 8; i++) xv[i] = x[base + (size_t)(d0 + i) * 4096u];
    float ls = 0.f;
    #pragma unroll
    for (int i = 0; i < 8; i++) {
        float t = qv[i] - xv[i];
        qout[base + (size_t)(d0 + i) * 4096u] = xv[i] + t;
        ls = fmaf(t, t, ls);
    }

    float* dst = g_dw + k * D_DIM + d0;
    asm volatile("red.global.add.v4.f32 [%0], {%1,%2,%3,%4};"
                 :: "l"(dst), "f"(xv[0]), "f"(xv[1]), "f"(xv[2]), "f"(xv[3]) : "memory");
    asm volatile("red.global.add.v4.f32 [%0], {%1,%2,%3,%4};"
                 :: "l"(dst + 4), "f"(xv[4]), "f"(xv[5]), "f"(xv[6]), "f"(xv[7]) : "memory");

    #pragma unroll
    for (int o = 16; o; o >>= 1) ls += __shfl_down_sync(0xffffffffu, ls, o);
    __shared__ float ws[8];
    int tid = threadIdx.x;
    if ((tid & 31) == 0) ws[tid >> 5] = ls;
    __syncthreads();
    if (tid == 0) {
        float sum = 0.f;
        #pragma unroll
        for (int i = 0; i < 8; i++) sum += ws[i];
        g_partials[blockIdx.y * 32 + blockIdx.x] = sum;
    }
}

// ---------------- merged finalize: cs + new_embed + loss ----------------
__global__ void __launch_bounds__(256) k_fin2(const float* __restrict__ cluster_size,
                                              const float* __restrict__ embed_avg,
                                              float* __restrict__ loss_out,
                                              float* __restrict__ out_e)
{
    __shared__ float sb[256];
    int k = blockIdx.x, t = threadIdx.x;
    float part = 0.f;
    #pragma unroll
    for (int i = 0; i < 4; i++) {
        int c = t + i * 256;
        part += cluster_size[c] * 0.99f + 0.01f * g_batch_cs[c];
    }
    sb[t] = part; __syncthreads();
    for (int o = 128; o; o >>= 1) { if (t < o) sb[t] += sb[t + o]; __syncthreads(); }
    float nsum = sb[0];
    float ncs = cluster_size[k] * 0.99f + 0.01f * g_batch_cs[k];
    float cs = nsum * (ncs + 1e-5f) / (nsum + 1024.0f * 1e-5f);
    int o_ = k * D_DIM + t;
    out_e[o_] = (embed_avg[o_] * 0.99f + 0.01f * g_dw[o_]) / cs;

    if (k == 0) {
        __syncthreads();
        float s = 0.f;
        for (int i = t; i < 32 * 128; i += 256) s += g_partials[i];
        sb[t] = s; __syncthreads();
        for (int o = 128; o; o >>= 1) { if (t < o) sb[t] += sb[t + o]; __syncthreads(); }
        if (t == 0) loss_out[0] = 0.25f * sb[0] / (float)Q_ELEMS;
    }
}

// ---------------- launch ----------------
extern "C" void kernel_launch(void* const* d_in, const int* in_sizes, int n_in,
                              void* d_out, int out_size)
{
    const float* x         = (const float*)d_in[0];
    const float* embed     = (const float*)d_in[1];
    const float* embed_avg = (const float*)d_in[2];
    const float* cluster   = (const float*)d_in[3];

    float* out     = (float*)d_out;
    float* out_q   = out + 1;
    float* out_idx = out_q + Q_ELEMS;
    float* out_e   = out_idx + N_TOK;

    void *p_dw, *p_bc, *p_fc, *p_f2;
    cudaGetSymbolAddress(&p_dw, g_dw);
    cudaGetSymbolAddress(&p_bc, g_batch_cs);
    cudaGetSymbolAddress(&p_fc, g_flag_cnt);
    cudaGetSymbolAddress(&p_f2, g_flag2_cnt);
    cudaMemsetAsync(p_dw, 0, sizeof(float) * K_CODES * D_DIM, 0);
    cudaMemsetAsync(p_bc, 0, sizeof(float) * K_CODES, 0);
    cudaMemsetAsync(p_fc, 0, sizeof(int), 0);
    cudaMemsetAsync(p_f2, 0, sizeof(int), 0);

    cudaFuncSetAttribute(k_argmin,   cudaFuncAttributeMaxDynamicSharedMemorySize, SM_TOTAL);
    cudaFuncSetAttribute(k_rescue_t, cudaFuncAttributeMaxDynamicSharedMemorySize, RS_TOTAL);

    k_esplit<<<K_CODES, D_DIM>>>(embed);
    k_argmin<<<256, 256, SM_TOTAL>>>(x);
    k_rescue_t<<<96, 256, RS_TOTAL>>>(x);
    dim3 ge(128, 8);
    k_rescue_exact<<<ge, 256>>>(x, embed);
    k_rescue_fin<<<1, 256>>>();
    dim3 g(32, 128);
    k_quant_dw<<<g, 256>>>(x, embed, out_q, out_idx);
    k_fin2<<<K_CODES, D_DIM>>>(cluster, embed_avg, out, out_e);
}

// round 13
// speedup vs baseline: 1.0847x; 1.0847x over previous
#include <cuda_runtime.h>
#include <cuda_bf16.h>
#include <stdint.h>

typedef unsigned u32; typedef unsigned long long u64;

#define K_CODES 1024
#define D_DIM   256
#define N_TOK   32768
#define Q_ELEMS (8u*256u*4096u)
#define TAU     0.75f
#define TAU2    0.003f

#define XPITCH  264        /* x smem row pitch in bf16 elements (528 B) */
#define BPITCH  144        /* e tile row pitch in bytes (128 data + 16) */
#define SM_BT   18432      /* one 128-code x 64-d bf16 tile             */

/* main kernel smem map */
#define SM_XH   0
#define SM_B    67584
#define SM_TOTAL (67584 + 2 * SM_BT)          /* 104448 */

/* tensor-rescue smem map: 32 tokens/CTA (R9 optimum) */
#define RS_XH   0
#define RS_XL   16896
#define RS_B    33792
#define RS_TOTAL (33792 + 4 * SM_BT)          /* 107520 */

// ---------------- device scratch ----------------
__device__ __align__(16) __nv_bfloat16 g_Ebf[2][K_CODES][D_DIM];  // hi/lo of -2*embed
__device__ float g_e2[K_CODES];
__device__ int   g_idx[N_TOK];
__device__ float g_batch_cs[K_CODES];
__device__ float g_dw[K_CODES * D_DIM];
__device__ float g_partials[32 * 128];
__device__ int   g_flag_cnt;
__device__ int   g_flag_tok[N_TOK];
__device__ int   g_flag2_cnt;
__device__ int   g_flag2_tok[N_TOK];
__device__ u64   g_best2[N_TOK];

// ---------------- helpers ----------------
__device__ __forceinline__ u32 smem_u32(const void* p) {
    u32 a; asm("{ .reg .u64 t; cvta.to.shared.u64 t, %1; cvt.u32.u64 %0, t; }" : "=r"(a) : "l"(p)); return a;
}
__device__ __forceinline__ u32 fkey(float v) {
    u32 u = __float_as_uint(v); return (u & 0x80000000u) ? ~u : (u | 0x80000000u);
}
__device__ __forceinline__ float fkeyinv(u32 k) {
    u32 u = (k & 0x80000000u) ? (k & 0x7FFFFFFFu) : ~k; return __uint_as_float(u);
}
__device__ __forceinline__ void cpa16(u32 dst, const void* src) {
    asm volatile("cp.async.cg.shared.global [%0], [%1], 16;" :: "r"(dst), "l"(src));
}
#define CP_COMMIT() asm volatile("cp.async.commit_group;" ::: "memory")
#define CP_WAIT1()  asm volatile("cp.async.wait_group 1;" ::: "memory")
#define CP_WAIT0()  asm volatile("cp.async.wait_group 0;" ::: "memory")

__device__ __forceinline__ void ldm4(u32& r0, u32& r1, u32& r2, u32& r3, u32 a) {
    asm volatile("ldmatrix.sync.aligned.m8n8.x4.shared.b16 {%0,%1,%2,%3}, [%4];"
                 : "=r"(r0), "=r"(r1), "=r"(r2), "=r"(r3) : "r"(a));
}
__device__ __forceinline__ void mma16816(float* c, const u32* a, const u32* b) {
    asm volatile("mma.sync.aligned.m16n8k16.row.col.f32.bf16.bf16.f32 "
                 "{%0,%1,%2,%3}, {%4,%5,%6,%7}, {%8,%9}, {%0,%1,%2,%3};"
                 : "+f"(c[0]), "+f"(c[1]), "+f"(c[2]), "+f"(c[3])
                 : "r"(a[0]), "r"(a[1]), "r"(a[2]), "r"(a[3]), "r"(b[0]), "r"(b[1]));
}
__device__ __forceinline__ void track(u64& b1, u32& b2, u64 pk) {
    if (pk < b1) { b2 = min(b2, (u32)(b1 >> 32)); b1 = pk; }
    else         { b2 = min(b2, (u32)(pk >> 32)); }
}

// ---------------- prep: bf16 hi/lo of -2*embed + e2 ----------------
__global__ void k_esplit(const float* __restrict__ embed) {
    int k = blockIdx.x, d = threadIdx.x;
    float e = embed[k * D_DIM + d];
    float v = -2.0f * e;
    __nv_bfloat16 h = __float2bfloat16(v);
    g_Ebf[0][k][d] = h;
    g_Ebf[1][k][d] = __float2bfloat16(v - __bfloat162float(h));
    float s = e * e;
    #pragma unroll
    for (int o = 16; o; o >>= 1) s += __shfl_down_sync(0xffffffffu, s, o);
    __shared__ float ws[8];
    if ((d & 31) == 0) ws[d >> 5] = s;
    __syncthreads();
    if (d == 0) {
        float t = 0.f;
        #pragma unroll
        for (int i = 0; i < 8; i++) t += ws[i];
        g_e2[k] = t;
    }
}

// ---------------- level 1: single-pass xh*eh GEMM over all tokens ----------------
__global__ void __launch_bounds__(256, 1) k_argmin(const float* __restrict__ x) {
    extern __shared__ __align__(128) char smem[];
    u32 smb = smem_u32(smem);
    const int tid = threadIdx.x, l = tid & 31, wid = tid >> 5;
    const int wm = wid & 3, wn = wid >> 2;
    const int m0 = blockIdx.x * 128;
    const int b = m0 >> 12, s0 = m0 & 4095;

    __nv_bfloat16* xh = (__nv_bfloat16*)(smem + SM_XH);
    {   // fill x tile (hi only): [128 tok][256 d]
        int tok = tid & 127, dh = tid >> 7;
        const float* xp = x + (size_t)b * 1048576u + s0 + tok;
        #pragma unroll 4
        for (int i = 0; i < 128; i++) {
            int d = dh + 2 * i;
            xh[tok * XPITCH + d] = __float2bfloat16(xp[(size_t)d * 4096u]);
        }
    }

    auto prefetch = [&](int step) {
        int tile = step >> 2, chunk = step & 3;
        u32 dst = smb + SM_B + (u32)(step & 1) * SM_BT;
        const char* src0 = (const char*)&g_Ebf[0][tile * 128][0] + chunk * 128;
        #pragma unroll
        for (int i = 0; i < 4; i++) {
            int idx = tid + i * 256;
            int crow = idx >> 3, seg = idx & 7;
            cpa16(dst + crow * BPITCH + seg * 16, src0 + (size_t)crow * 512 + seg * 16);
        }
        CP_COMMIT();
    };

    float acc[2][8][4];
    u64 b1[4]; u32 b2[4];
    #pragma unroll
    for (int q = 0; q < 4; q++) { b1[q] = ~0ull; b2[q] = 0xFFFFFFFFu; }
    #pragma unroll
    for (int mt = 0; mt < 2; mt++)
        #pragma unroll
        for (int nt = 0; nt < 8; nt++)
            #pragma unroll
            for (int r = 0; r < 4; r++) acc[mt][nt][r] = 0.f;

    __syncthreads();
    prefetch(0);

    const u32 aoff = (u32)((l & 7) + ((l >> 3) & 1) * 8) * 528 + ((l >> 4) & 1) * 16;
    const u32 boff = (u32)((l & 7) + ((l >> 4) & 1) * 8) * BPITCH + ((l >> 3) & 1) * 16;

    for (int step = 0; step < 32; step++) {
        int tile = step >> 2, chunk = step & 3;
        if (step < 31) { prefetch(step + 1); CP_WAIT1(); } else { CP_WAIT0(); }
        __syncthreads();
        u32 Bb = smb + SM_B + (u32)(step & 1) * SM_BT;
        #pragma unroll
        for (int ks = 0; ks < 4; ks++) {
            u32 kbyte = (u32)chunk * 128 + ks * 32;
            u32 ah[2][4];
            #pragma unroll
            for (int mt = 0; mt < 2; mt++)
                ldm4(ah[mt][0], ah[mt][1], ah[mt][2], ah[mt][3],
                     smb + SM_XH + (u32)(wm * 32 + mt * 16) * 528 + kbyte + aoff);
            u32 bb[4][4];
            #pragma unroll
            for (int ng = 0; ng < 4; ng++)
                ldm4(bb[ng][0], bb[ng][1], bb[ng][2], bb[ng][3],
                     Bb + (u32)(wn * 64 + ng * 16) * BPITCH + ks * 32 + boff);
            #pragma unroll
            for (int mt = 0; mt < 2; mt++)
                #pragma unroll
                for (int ng = 0; ng < 4; ng++) {
                    mma16816(acc[mt][ng * 2],     ah[mt], &bb[ng][0]);
                    mma16816(acc[mt][ng * 2 + 1], ah[mt], &bb[ng][2]);
                }
        }
        if (chunk == 3) {
            float2 e2v[8];
            #pragma unroll
            for (int nt = 0; nt < 8; nt++)
                e2v[nt] = *(const float2*)(g_e2 + tile * 128 + wn * 64 + nt * 8 + 2 * (l & 3));
            #pragma unroll
            for (int mt = 0; mt < 2; mt++)
                #pragma unroll
                for (int nt = 0; nt < 8; nt++)
                    #pragma unroll
                    for (int r = 0; r < 4; r++) {
                        float v = acc[mt][nt][r] + ((r & 1) ? e2v[nt].y : e2v[nt].x);
                        u32 col = (u32)(tile * 128 + wn * 64 + nt * 8 + 2 * (l & 3) + (r & 1));
                        track(b1[mt * 2 + (r >> 1)], b2[mt * 2 + (r >> 1)],
                              ((u64)fkey(v) << 32) | col);
                        acc[mt][nt][r] = 0.f;
                    }
        }
        __syncthreads();
    }

    // merge lanes (l&3) sharing each row
    #pragma unroll
    for (int tr = 0; tr < 4; tr++)
        #pragma unroll
        for (int off = 1; off <= 2; off <<= 1) {
            u64 o1 = __shfl_xor_sync(0xffffffffu, b1[tr], off);
            u32 o2 = __shfl_xor_sync(0xffffffffu, b2[tr], off);
            u64 mx = (b1[tr] > o1) ? b1[tr] : o1;
            b1[tr] = (b1[tr] < o1) ? b1[tr] : o1;
            b2[tr] = min(min(b2[tr], o2), (u32)(mx >> 32));
        }
    u64* tab1 = (u64*)(smem + SM_B);
    u32* tab2 = (u32*)(smem + SM_B + 2048);
    if ((l & 3) == 0)
        #pragma unroll
        for (int tr = 0; tr < 4; tr++) {
            int row = wm * 32 + (tr >> 1) * 16 + (tr & 1) * 8 + (l >> 2);
            tab1[row * 2 + wn] = b1[tr];
            tab2[row * 2 + wn] = b2[tr];
        }
    __syncthreads();
    if (tid < 128) {
        u64 p = tab1[tid * 2], q = tab1[tid * 2 + 1];
        u64 best = p < q ? p : q, worse = p < q ? q : p;
        u32 sec = min(min(tab2[tid * 2], tab2[tid * 2 + 1]), (u32)(worse >> 32));
        int n = m0 + tid;
        g_idx[n] = (int)(best & 0xFFFFFFFFull);
        float margin = fkeyinv(sec) - fkeyinv((u32)(best >> 32));
        if (!(margin > TAU)) { int pp = atomicAdd(&g_flag_cnt, 1); g_flag_tok[pp] = n; }
    }
}

// ---------------- level 2: 3-pass tensor rescue, 32 flagged tokens / CTA ----------------
__global__ void __launch_bounds__(256, 1) k_rescue_t(const float* __restrict__ x) {
    extern __shared__ __align__(128) char smem[];
    u32 smb = smem_u32(smem);
    const int tid = threadIdx.x, l = tid & 31, wn = tid >> 5;   // 8 warps, 16 codes each
    int cnt = *((volatile int*)&g_flag_cnt);
    int G = (cnt + 31) >> 5;

    const u32 aoff = (u32)((l & 7) + ((l >> 3) & 1) * 8) * 528 + ((l >> 4) & 1) * 16;
    const u32 boff = (u32)((l & 7) + ((l >> 4) & 1) * 8) * BPITCH + ((l >> 3) & 1) * 16;
    __nv_bfloat16* xh = (__nv_bfloat16*)(smem + RS_XH);
    __nv_bfloat16* xl = (__nv_bfloat16*)(smem + RS_XL);

    for (int g = blockIdx.x; g < G; g += gridDim.x) {
        {   // gather 32 flagged tokens into smem hi/lo
            int slot = tid >> 3, seg = tid & 7;
            int li = g * 32 + slot;
            int n = g_flag_tok[li < cnt ? li : cnt - 1];
            int b = n >> 12, s = n & 4095;
            const float* xp = x + (size_t)b * 1048576u + s;
            #pragma unroll 4
            for (int i = 0; i < 32; i++) {
                int d = seg * 32 + i;
                float v = xp[(size_t)d * 4096u];
                __nv_bfloat16 h = __float2bfloat16(v);
                xh[slot * XPITCH + d] = h;
                xl[slot * XPITCH + d] = __float2bfloat16(v - __bfloat162float(h));
            }
        }

        auto prefetch = [&](int step) {
            int tile = step >> 2, chunk = step & 3;
            u32 dstb = smb + RS_B + (u32)(step & 1) * (2 * SM_BT);
            #pragma unroll
            for (int op = 0; op < 2; op++) {
                const char* src0 = (const char*)&g_Ebf[op][tile * 128][0] + chunk * 128;
                u32 dst = dstb + op * SM_BT;
                #pragma unroll
                for (int i = 0; i < 4; i++) {
                    int idx = tid + i * 256;
                    int crow = idx >> 3, seg = idx & 7;
                    cpa16(dst + crow * BPITCH + seg * 16, src0 + (size_t)crow * 512 + seg * 16);
                }
            }
            CP_COMMIT();
        };

        float acc[2][2][4];
        u64 b1[4]; u32 b2[4];
        #pragma unroll
        for (int q = 0; q < 4; q++) { b1[q] = ~0ull; b2[q] = 0xFFFFFFFFu; }
        #pragma unroll
        for (int mt = 0; mt < 2; mt++)
            #pragma unroll
            for (int nh = 0; nh < 2; nh++)
                #pragma unroll
                for (int r = 0; r < 4; r++) acc[mt][nh][r] = 0.f;

        __syncthreads();
        prefetch(0);

        for (int step = 0; step < 32; step++) {
            int tile = step >> 2, chunk = step & 3;
            if (step < 31) { prefetch(step + 1); CP_WAIT1(); } else { CP_WAIT0(); }
            __syncthreads();
            u32 Bb = smb + RS_B + (u32)(step & 1) * (2 * SM_BT);
            #pragma unroll
            for (int ks = 0; ks < 4; ks++) {
                u32 kbyte = (u32)chunk * 128 + ks * 32;
                u32 ah[2][4], al[2][4], bh[4], bl[4];
                #pragma unroll
                for (int mt = 0; mt < 2; mt++) {
                    u32 rowb = (u32)(mt * 16) * 528 + kbyte + aoff;
                    ldm4(ah[mt][0], ah[mt][1], ah[mt][2], ah[mt][3], smb + RS_XH + rowb);
                    ldm4(al[mt][0], al[mt][1], al[mt][2], al[mt][3], smb + RS_XL + rowb);
                }
                u32 brow = (u32)(wn * 16) * BPITCH + ks * 32 + boff;
                ldm4(bh[0], bh[1], bh[2], bh[3], Bb + brow);
                ldm4(bl[0], bl[1], bl[2], bl[3], Bb + SM_BT + brow);
                #pragma unroll
                for (int mt = 0; mt < 2; mt++) {
                    mma16816(acc[mt][0], ah[mt], &bh[0]);
                    mma16816(acc[mt][1], ah[mt], &bh[2]);
                    mma16816(acc[mt][0], ah[mt], &bl[0]);
                    mma16816(acc[mt][1], ah[mt], &bl[2]);
                    mma16816(acc[mt][0], al[mt], &bh[0]);
                    mma16816(acc[mt][1], al[mt], &bh[2]);
                }
            }
            if (chunk == 3) {
                float2 e2v[2];
                #pragma unroll
                for (int nh = 0; nh < 2; nh++)
                    e2v[nh] = *(const float2*)(g_e2 + tile * 128 + wn * 16 + nh * 8 + 2 * (l & 3));
                #pragma unroll
                for (int mt = 0; mt < 2; mt++)
                    #pragma unroll
                    for (int nh = 0; nh < 2; nh++)
                        #pragma unroll
                        for (int r = 0; r < 4; r++) {
                            float v = acc[mt][nh][r] + ((r & 1) ? e2v[nh].y : e2v[nh].x);
                            u32 col = (u32)(tile * 128 + wn * 16 + nh * 8 + 2 * (l & 3) + (r & 1));
                            track(b1[mt * 2 + (r >> 1)], b2[mt * 2 + (r >> 1)],
                                  ((u64)fkey(v) << 32) | col);
                            acc[mt][nh][r] = 0.f;
                        }
            }
            __syncthreads();
        }

        #pragma unroll
        for (int tr = 0; tr < 4; tr++)
            #pragma unroll
            for (int off = 1; off <= 2; off <<= 1) {
                u64 o1 = __shfl_xor_sync(0xffffffffu, b1[tr], off);
                u32 o2 = __shfl_xor_sync(0xffffffffu, b2[tr], off);
                u64 mx = (b1[tr] > o1) ? b1[tr] : o1;
                b1[tr] = (b1[tr] < o1) ? b1[tr] : o1;
                b2[tr] = min(min(b2[tr], o2), (u32)(mx >> 32));
            }
        u64* tab1 = (u64*)(smem + RS_B);
        u32* tab2 = (u32*)(smem + RS_B + 2048);
        if ((l & 3) == 0)
            #pragma unroll
            for (int tr = 0; tr < 4; tr++) {
                int row = (tr >> 1) * 16 + (tr & 1) * 8 + (l >> 2);
                tab1[row * 8 + wn] = b1[tr];
                tab2[row * 8 + wn] = b2[tr];
            }
        __syncthreads();
        if (tid < 32) {
            u64 best = ~0ull; u32 sec = 0xFFFFFFFFu;
            #pragma unroll
            for (int w = 0; w < 8; w++) {
                u64 p = tab1[tid * 8 + w];
                if (p < best) { sec = min(sec, (u32)(best >> 32)); best = p; }
                else          { sec = min(sec, (u32)(p >> 32)); }
                sec = min(sec, tab2[tid * 8 + w]);
            }
            int li = g * 32 + tid;
            if (li < cnt) {
                int n = g_flag_tok[li];
                float margin = fkeyinv(sec) - fkeyinv((u32)(best >> 32));
                if (margin > TAU2) g_idx[n] = (int)(best & 0xFFFFFFFFull);
                else {
                    int pp = atomicAdd(&g_flag2_cnt, 1);
                    g_flag2_tok[pp] = n;
                    g_best2[pp] = ~0ull;
                }
            }
        }
        __syncthreads();
    }
}

// ---------------- level 3: exact fp32, parallel over (token, 128-code chunk) ----------------
__global__ void __launch_bounds__(256) k_rescue_exact(const float* __restrict__ x,
                                                      const float* __restrict__ embed) {
    __shared__ float xs[256];
    __shared__ float part[256];
    __shared__ u64 red[128];
    int tid = threadIdx.x;
    int cnt = *((volatile int*)&g_flag2_cnt);
    int code = blockIdx.y * 128 + (tid & 127);
    int half = tid >> 7;
    for (int i = blockIdx.x; i < cnt; i += gridDim.x) {
        int n = g_flag2_tok[i];
        int b = n >> 12, s = n & 4095;
        xs[tid] = x[(size_t)b * 1048576u + (size_t)tid * 4096u + s];
        __syncthreads();
        const float4* e4 = (const float4*)(embed + code * 256) + half * 32;
        const float* xsp = xs + half * 128;
        float acc = 0.f;
        #pragma unroll 8
        for (int q = 0; q < 32; q++) {
            float4 ev = e4[q];
            acc = fmaf(ev.x, xsp[q*4+0], acc);
            acc = fmaf(ev.y, xsp[q*4+1], acc);
            acc = fmaf(ev.z, xsp[q*4+2], acc);
            acc = fmaf(ev.w, xsp[q*4+3], acc);
        }
        part[tid] = acc;
        __syncthreads();
        if (tid < 128) {
            float sc = g_e2[code] - 2.f * (part[tid] + part[tid + 128]);
            red[tid] = ((u64)fkey(sc) << 32) | (u32)code;
        }
        __syncthreads();
        for (int o = 64; o; o >>= 1) {
            if (tid < o) red[tid] = min(red[tid], red[tid + o]);
            __syncthreads();
        }
        if (tid == 0) atomicMin(&g_best2[i], red[0]);
        __syncthreads();
    }
}

__global__ void k_rescue_fin() {
    int cnt = *((volatile int*)&g_flag2_cnt);
    for (int i = threadIdx.x; i < cnt; i += blockDim.x)
        g_idx[g_flag2_tok[i]] = (int)(g_best2[i] & 0xFFFFFFFFull);
}

// ---------------- fused quantized write + loss + dw scatter + idx out ----------------
__global__ void k_quant_dw(const float* __restrict__ x,
                           const float* __restrict__ embed,
                           float* __restrict__ qout, float* __restrict__ idxf_out)
{
    int d0 = blockIdx.x << 3;
    int n  = (blockIdx.y << 8) + threadIdx.x;
    int b = n >> 12, s = n & 4095;
    size_t base = (size_t)b * 1048576u + s;
    int k = g_idx[n];
    float4 q0 = *(const float4*)(embed + k * D_DIM + d0);
    float4 q1 = *(const float4*)(embed + k * D_DIM + d0 + 4);
    if (blockIdx.x == 0) { idxf_out[n] = (float)k; atomicAdd(&g_batch_cs[k], 1.0f); }

    float xv[8], qv[8] = {q0.x, q0.y, q0.z, q0.w, q1.x, q1.y, q1.z, q1.w};
    #pragma unroll
    for (int i = 0; i < 8; i++) xv[i] = x[base + (size_t)(d0 + i) * 4096u];
    float ls = 0.f;
    #pragma unroll
    for (int i = 0; i < 8; i++) {
        float t = qv[i] - xv[i];
        qout[base + (size_t)(d0 + i) * 4096u] = xv[i] + t;
        ls = fmaf(t, t, ls);
    }

    float* dst = g_dw + k * D_DIM + d0;
    asm volatile("red.global.add.v4.f32 [%0], {%1,%2,%3,%4};"
                 :: "l"(dst), "f"(xv[0]), "f"(xv[1]), "f"(xv[2]), "f"(xv[3]) : "memory");
    asm volatile("red.global.add.v4.f32 [%0], {%1,%2,%3,%4};"
                 :: "l"(dst + 4), "f"(xv[4]), "f"(xv[5]), "f"(xv[6]), "f"(xv[7]) : "memory");

    #pragma unroll
    for (int o = 16; o; o >>= 1) ls += __shfl_down_sync(0xffffffffu, ls, o);
    __shared__ float ws[8];
    int tid = threadIdx.x;
    if ((tid & 31) == 0) ws[tid >> 5] = ls;
    __syncthreads();
    if (tid == 0) {
        float sum = 0.f;
        #pragma unroll
        for (int i = 0; i < 8; i++) sum += ws[i];
        g_partials[blockIdx.y * 32 + blockIdx.x] = sum;
    }
}

// ---------------- merged finalize: cs + new_embed + loss ----------------
__global__ void __launch_bounds__(256) k_fin2(const float* __restrict__ cluster_size,
                                              const float* __restrict__ embed_avg,
                                              float* __restrict__ loss_out,
                                              float* __restrict__ out_e)
{
    __shared__ float sb[256];
    int k = blockIdx.x, t = threadIdx.x;
    float part = 0.f;
    #pragma unroll
    for (int i = 0; i < 4; i++) {
        int c = t + i * 256;
        part += cluster_size[c] * 0.99f + 0.01f * g_batch_cs[c];
    }
    sb[t] = part; __syncthreads();
    for (int o = 128; o; o >>= 1) { if (t < o) sb[t] += sb[t + o]; __syncthreads(); }
    float nsum = sb[0];
    float ncs = cluster_size[k] * 0.99f + 0.01f * g_batch_cs[k];
    float cs = nsum * (ncs + 1e-5f) / (nsum + 1024.0f * 1e-5f);
    int o_ = k * D_DIM + t;
    out_e[o_] = (embed_avg[o_] * 0.99f + 0.01f * g_dw[o_]) / cs;

    if (k == 0) {
        __syncthreads();
        float s = 0.f;
        for (int i = t; i < 32 * 128; i += 256) s += g_partials[i];
        sb[t] = s; __syncthreads();
        for (int o = 128; o; o >>= 1) { if (t < o) sb[t] += sb[t + o]; __syncthreads(); }
        if (t == 0) loss_out[0] = 0.25f * sb[0] / (float)Q_ELEMS;
    }
}

// ---------------- launch ----------------
extern "C" void kernel_launch(void* const* d_in, const int* in_sizes, int n_in,
                              void* d_out, int out_size)
{
    const float* x         = (const float*)d_in[0];
    const float* embed     = (const float*)d_in[1];
    const float* embed_avg = (const float*)d_in[2];
    const float* cluster   = (const float*)d_in[3];

    float* out     = (float*)d_out;
    float* out_q   = out + 1;
    float* out_idx = out_q + Q_ELEMS;
    float* out_e   = out_idx + N_TOK;

    void *p_dw, *p_bc, *p_fc, *p_f2;
    cudaGetSymbolAddress(&p_dw, g_dw);
    cudaGetSymbolAddress(&p_bc, g_batch_cs);
    cudaGetSymbolAddress(&p_fc, g_flag_cnt);
    cudaGetSymbolAddress(&p_f2, g_flag2_cnt);
    cudaMemsetAsync(p_dw, 0, sizeof(float) * K_CODES * D_DIM, 0);
    cudaMemsetAsync(p_bc, 0, sizeof(float) * K_CODES, 0);
    cudaMemsetAsync(p_fc, 0, sizeof(int), 0);
    cudaMemsetAsync(p_f2, 0, sizeof(int), 0);

    cudaFuncSetAttribute(k_argmin,   cudaFuncAttributeMaxDynamicSharedMemorySize, SM_TOTAL);
    cudaFuncSetAttribute(k_rescue_t, cudaFuncAttributeMaxDynamicSharedMemorySize, RS_TOTAL);

    k_esplit<<<K_CODES, D_DIM>>>(embed);
    k_argmin<<<256, 256, SM_TOTAL>>>(x);
    k_rescue_t<<<192, 256, RS_TOTAL>>>(x);
    dim3 ge(128, 8);
    k_rescue_exact<<<ge, 256>>>(x, embed);
    k_rescue_fin<<<1, 256>>>();
    dim3 g(32, 128);
    k_quant_dw<<<g, 256>>>(x, embed, out_q, out_idx);
    k_fin2<<<K_CODES, D_DIM>>>(cluster, embed_avg, out, out_e);
}

// round 14
// speedup vs baseline: 1.1875x; 1.0948x over previous
#include <cuda_runtime.h>
#include <cuda_bf16.h>
#include <stdint.h>

typedef unsigned u32; typedef unsigned long long u64;

#define K_CODES 1024
#define D_DIM   256
#define N_TOK   32768
#define Q_ELEMS (8u*256u*4096u)
#define TAU     0.75f
#define TAU2    0.003f

#define XPITCH  264        /* x smem row pitch in bf16 elements (528 B) */
#define BPITCH  144        /* e tile row pitch in bytes (128 data + 16) */
#define SM_BT   18432      /* one 128-code x 64-d bf16 tile             */

/* main kernel smem map */
#define SM_XH   0
#define SM_B    67584
#define SM_TOTAL (67584 + 2 * SM_BT)          /* 104448 */

/* tensor-rescue smem map: 32 tokens/CTA */
#define RS_XH   0
#define RS_XL   16896
#define RS_B    33792
#define RS_TOTAL (33792 + 4 * SM_BT)          /* 107520 */

// ---------------- device scratch ----------------
__device__ __align__(16) __nv_bfloat16 g_Ebf[2][K_CODES][D_DIM];  // hi/lo of -2*embed
__device__ float g_e2[K_CODES];
__device__ int   g_idx[N_TOK];
__device__ float g_batch_cs[K_CODES];
__device__ float g_dw[K_CODES * D_DIM];
__device__ float g_partials[32 * 128];
__device__ int   g_flag_cnt;
__device__ int   g_flag_tok[N_TOK];
__device__ int   g_flag2_cnt;
__device__ int   g_flag2_tok[N_TOK];
__device__ u64   g_best2[N_TOK];

// ---------------- helpers ----------------
__device__ __forceinline__ u32 smem_u32(const void* p) {
    u32 a; asm("{ .reg .u64 t; cvta.to.shared.u64 t, %1; cvt.u32.u64 %0, t; }" : "=r"(a) : "l"(p)); return a;
}
__device__ __forceinline__ u32 fkey(float v) {
    u32 u = __float_as_uint(v); return (u & 0x80000000u) ? ~u : (u | 0x80000000u);
}
__device__ __forceinline__ float fkeyinv(u32 k) {
    u32 u = (k & 0x80000000u) ? (k & 0x7FFFFFFFu) : ~k; return __uint_as_float(u);
}
__device__ __forceinline__ void cpa16(u32 dst, const void* src) {
    asm volatile("cp.async.cg.shared.global [%0], [%1], 16;" :: "r"(dst), "l"(src));
}
#define CP_COMMIT() asm volatile("cp.async.commit_group;" ::: "memory")
#define CP_WAIT1()  asm volatile("cp.async.wait_group 1;" ::: "memory")
#define CP_WAIT0()  asm volatile("cp.async.wait_group 0;" ::: "memory")

__device__ __forceinline__ void ldm4(u32& r0, u32& r1, u32& r2, u32& r3, u32 a) {
    asm volatile("ldmatrix.sync.aligned.m8n8.x4.shared.b16 {%0,%1,%2,%3}, [%4];"
                 : "=r"(r0), "=r"(r1), "=r"(r2), "=r"(r3) : "r"(a));
}
__device__ __forceinline__ void mma16816(float* c, const u32* a, const u32* b) {
    asm volatile("mma.sync.aligned.m16n8k16.row.col.f32.bf16.bf16.f32 "
                 "{%0,%1,%2,%3}, {%4,%5,%6,%7}, {%8,%9}, {%0,%1,%2,%3};"
                 : "+f"(c[0]), "+f"(c[1]), "+f"(c[2]), "+f"(c[3])
                 : "r"(a[0]), "r"(a[1]), "r"(a[2]), "r"(a[3]), "r"(b[0]), "r"(b[1]));
}
__device__ __forceinline__ void track(u64& b1, u32& b2, u64 pk) {
    if (pk < b1) { b2 = min(b2, (u32)(b1 >> 32)); b1 = pk; }
    else         { b2 = min(b2, (u32)(pk >> 32)); }
}

// ---------------- prep: bf16 hi/lo of -2*embed + e2 ----------------
__global__ void k_esplit(const float* __restrict__ embed) {
    int k = blockIdx.x, d = threadIdx.x;
    float e = embed[k * D_DIM + d];
    float v = -2.0f * e;
    __nv_bfloat16 h = __float2bfloat16(v);
    g_Ebf[0][k][d] = h;
    g_Ebf[1][k][d] = __float2bfloat16(v - __bfloat162float(h));
    float s = e * e;
    #pragma unroll
    for (int o = 16; o; o >>= 1) s += __shfl_down_sync(0xffffffffu, s, o);
    __shared__ float ws[8];
    if ((d & 31) == 0) ws[d >> 5] = s;
    __syncthreads();
    if (d == 0) {
        float t = 0.f;
        #pragma unroll
        for (int i = 0; i < 8; i++) t += ws[i];
        g_e2[k] = t;
    }
}

// ---------------- level 1: single-pass xh*eh GEMM over all tokens ----------------
__global__ void __launch_bounds__(256, 2) k_argmin(const float* __restrict__ x) {
    extern __shared__ __align__(128) char smem[];
    u32 smb = smem_u32(smem);
    const int tid = threadIdx.x, l = tid & 31, wid = tid >> 5;
    const int wm = wid & 3, wn = wid >> 2;
    const int m0 = blockIdx.x * 128;
    const int b = m0 >> 12, s0 = m0 & 4095;

    __nv_bfloat16* xh = (__nv_bfloat16*)(smem + SM_XH);
    {   // fill x tile (hi only): [128 tok][256 d]
        int tok = tid & 127, dh = tid >> 7;
        const float* xp = x + (size_t)b * 1048576u + s0 + tok;
        #pragma unroll 4
        for (int i = 0; i < 128; i++) {
            int d = dh + 2 * i;
            xh[tok * XPITCH + d] = __float2bfloat16(xp[(size_t)d * 4096u]);
        }
    }

    auto prefetch = [&](int step) {
        int tile = step >> 2, chunk = step & 3;
        u32 dst = smb + SM_B + (u32)(step & 1) * SM_BT;
        const char* src0 = (const char*)&g_Ebf[0][tile * 128][0] + chunk * 128;
        #pragma unroll
        for (int i = 0; i < 4; i++) {
            int idx = tid + i * 256;
            int crow = idx >> 3, seg = idx & 7;
            cpa16(dst + crow * BPITCH + seg * 16, src0 + (size_t)crow * 512 + seg * 16);
        }
        CP_COMMIT();
    };

    float acc[2][8][4];
    u64 b1[4]; u32 b2[4];
    #pragma unroll
    for (int q = 0; q < 4; q++) { b1[q] = ~0ull; b2[q] = 0xFFFFFFFFu; }
    #pragma unroll
    for (int mt = 0; mt < 2; mt++)
        #pragma unroll
        for (int nt = 0; nt < 8; nt++)
            #pragma unroll
            for (int r = 0; r < 4; r++) acc[mt][nt][r] = 0.f;

    __syncthreads();
    prefetch(0);

    const u32 aoff = (u32)((l & 7) + ((l >> 3) & 1) * 8) * 528 + ((l >> 4) & 1) * 16;
    const u32 boff = (u32)((l & 7) + ((l >> 4) & 1) * 8) * BPITCH + ((l >> 3) & 1) * 16;

    for (int step = 0; step < 32; step++) {
        int tile = step >> 2, chunk = step & 3;
        if (step < 31) { prefetch(step + 1); CP_WAIT1(); } else { CP_WAIT0(); }
        __syncthreads();
        u32 Bb = smb + SM_B + (u32)(step & 1) * SM_BT;
        #pragma unroll
        for (int ks = 0; ks < 4; ks++) {
            u32 kbyte = (u32)chunk * 128 + ks * 32;
            u32 ah[2][4];
            #pragma unroll
            for (int mt = 0; mt < 2; mt++)
                ldm4(ah[mt][0], ah[mt][1], ah[mt][2], ah[mt][3],
                     smb + SM_XH + (u32)(wm * 32 + mt * 16) * 528 + kbyte + aoff);
            u32 bb[4][4];
            #pragma unroll
            for (int ng = 0; ng < 4; ng++)
                ldm4(bb[ng][0], bb[ng][1], bb[ng][2], bb[ng][3],
                     Bb + (u32)(wn * 64 + ng * 16) * BPITCH + ks * 32 + boff);
            #pragma unroll
            for (int mt = 0; mt < 2; mt++)
                #pragma unroll
                for (int ng = 0; ng < 4; ng++) {
                    mma16816(acc[mt][ng * 2],     ah[mt], &bb[ng][0]);
                    mma16816(acc[mt][ng * 2 + 1], ah[mt], &bb[ng][2]);
                }
        }
        if (chunk == 3) {
            float2 e2v[8];
            #pragma unroll
            for (int nt = 0; nt < 8; nt++)
                e2v[nt] = *(const float2*)(g_e2 + tile * 128 + wn * 64 + nt * 8 + 2 * (l & 3));
            #pragma unroll
            for (int mt = 0; mt < 2; mt++)
                #pragma unroll
                for (int nt = 0; nt < 8; nt++)
                    #pragma unroll
                    for (int r = 0; r < 4; r++) {
                        float v = acc[mt][nt][r] + ((r & 1) ? e2v[nt].y : e2v[nt].x);
                        u32 col = (u32)(tile * 128 + wn * 64 + nt * 8 + 2 * (l & 3) + (r & 1));
                        track(b1[mt * 2 + (r >> 1)], b2[mt * 2 + (r >> 1)],
                              ((u64)fkey(v) << 32) | col);
                        acc[mt][nt][r] = 0.f;
                    }
        }
        __syncthreads();
    }

    // merge lanes (l&3) sharing each row
    #pragma unroll
    for (int tr = 0; tr < 4; tr++)
        #pragma unroll
        for (int off = 1; off <= 2; off <<= 1) {
            u64 o1 = __shfl_xor_sync(0xffffffffu, b1[tr], off);
            u32 o2 = __shfl_xor_sync(0xffffffffu, b2[tr], off);
            u64 mx = (b1[tr] > o1) ? b1[tr] : o1;
            b1[tr] = (b1[tr] < o1) ? b1[tr] : o1;
            b2[tr] = min(min(b2[tr], o2), (u32)(mx >> 32));
        }
    u64* tab1 = (u64*)(smem + SM_B);
    u32* tab2 = (u32*)(smem + SM_B + 2048);
    if ((l & 3) == 0)
        #pragma unroll
        for (int tr = 0; tr < 4; tr++) {
            int row = wm * 32 + (tr >> 1) * 16 + (tr & 1) * 8 + (l >> 2);
            tab1[row * 2 + wn] = b1[tr];
            tab2[row * 2 + wn] = b2[tr];
        }
    __syncthreads();
    if (tid < 128) {
        u64 p = tab1[tid * 2], q = tab1[tid * 2 + 1];
        u64 best = p < q ? p : q, worse = p < q ? q : p;
        u32 sec = min(min(tab2[tid * 2], tab2[tid * 2 + 1]), (u32)(worse >> 32));
        int n = m0 + tid;
        g_idx[n] = (int)(best & 0xFFFFFFFFull);
        float margin = fkeyinv(sec) - fkeyinv((u32)(best >> 32));
        if (!(margin > TAU)) { int pp = atomicAdd(&g_flag_cnt, 1); g_flag_tok[pp] = n; }
    }
}

// ---------------- level 2: 3-pass tensor rescue, 32 flagged tokens / CTA ----------------
__global__ void __launch_bounds__(256, 2) k_rescue_t(const float* __restrict__ x) {
    extern __shared__ __align__(128) char smem[];
    u32 smb = smem_u32(smem);
    const int tid = threadIdx.x, l = tid & 31, wn = tid >> 5;   // 8 warps, 16 codes each
    int cnt = *((volatile int*)&g_flag_cnt);
    int G = (cnt + 31) >> 5;

    const u32 aoff = (u32)((l & 7) + ((l >> 3) & 1) * 8) * 528 + ((l >> 4) & 1) * 16;
    const u32 boff = (u32)((l & 7) + ((l >> 4) & 1) * 8) * BPITCH + ((l >> 3) & 1) * 16;
    __nv_bfloat16* xh = (__nv_bfloat16*)(smem + RS_XH);
    __nv_bfloat16* xl = (__nv_bfloat16*)(smem + RS_XL);

    for (int g = blockIdx.x; g < G; g += gridDim.x) {
        {   // gather 32 flagged tokens into smem hi/lo
            int slot = tid >> 3, seg = tid & 7;
            int li = g * 32 + slot;
            int n = g_flag_tok[li < cnt ? li : cnt - 1];
            int b = n >> 12, s = n & 4095;
            const float* xp = x + (size_t)b * 1048576u + s;
            #pragma unroll 4
            for (int i = 0; i < 32; i++) {
                int d = seg * 32 + i;
                float v = xp[(size_t)d * 4096u];
                __nv_bfloat16 h = __float2bfloat16(v);
                xh[slot * XPITCH + d] = h;
                xl[slot * XPITCH + d] = __float2bfloat16(v - __bfloat162float(h));
            }
        }

        auto prefetch = [&](int step) {
            int tile = step >> 2, chunk = step & 3;
            u32 dstb = smb + RS_B + (u32)(step & 1) * (2 * SM_BT);
            #pragma unroll
            for (int op = 0; op < 2; op++) {
                const char* src0 = (const char*)&g_Ebf[op][tile * 128][0] + chunk * 128;
                u32 dst = dstb + op * SM_BT;
                #pragma unroll
                for (int i = 0; i < 4; i++) {
                    int idx = tid + i * 256;
                    int crow = idx >> 3, seg = idx & 7;
                    cpa16(dst + crow * BPITCH + seg * 16, src0 + (size_t)crow * 512 + seg * 16);
                }
            }
            CP_COMMIT();
        };

        float acc[2][2][4];
        u64 b1[4]; u32 b2[4];
        #pragma unroll
        for (int q = 0; q < 4; q++) { b1[q] = ~0ull; b2[q] = 0xFFFFFFFFu; }
        #pragma unroll
        for (int mt = 0; mt < 2; mt++)
            #pragma unroll
            for (int nh = 0; nh < 2; nh++)
                #pragma unroll
                for (int r = 0; r < 4; r++) acc[mt][nh][r] = 0.f;

        __syncthreads();
        prefetch(0);

        for (int step = 0; step < 32; step++) {
            int tile = step >> 2, chunk = step & 3;
            if (step < 31) { prefetch(step + 1); CP_WAIT1(); } else { CP_WAIT0(); }
            __syncthreads();
            u32 Bb = smb + RS_B + (u32)(step & 1) * (2 * SM_BT);
            #pragma unroll
            for (int ks = 0; ks < 4; ks++) {
                u32 kbyte = (u32)chunk * 128 + ks * 32;
                u32 ah[2][4], al[2][4], bh[4], bl[4];
                #pragma unroll
                for (int mt = 0; mt < 2; mt++) {
                    u32 rowb = (u32)(mt * 16) * 528 + kbyte + aoff;
                    ldm4(ah[mt][0], ah[mt][1], ah[mt][2], ah[mt][3], smb + RS_XH + rowb);
                    ldm4(al[mt][0], al[mt][1], al[mt][2], al[mt][3], smb + RS_XL + rowb);
                }
                u32 brow = (u32)(wn * 16) * BPITCH + ks * 32 + boff;
                ldm4(bh[0], bh[1], bh[2], bh[3], Bb + brow);
                ldm4(bl[0], bl[1], bl[2], bl[3], Bb + SM_BT + brow);
                #pragma unroll
                for (int mt = 0; mt < 2; mt++) {
                    mma16816(acc[mt][0], ah[mt], &bh[0]);
                    mma16816(acc[mt][1], ah[mt], &bh[2]);
                    mma16816(acc[mt][0], ah[mt], &bl[0]);
                    mma16816(acc[mt][1], ah[mt], &bl[2]);
                    mma16816(acc[mt][0], al[mt], &bh[0]);
                    mma16816(acc[mt][1], al[mt], &bh[2]);
                }
            }
            if (chunk == 3) {
                float2 e2v[2];
                #pragma unroll
                for (int nh = 0; nh < 2; nh++)
                    e2v[nh] = *(const float2*)(g_e2 + tile * 128 + wn * 16 + nh * 8 + 2 * (l & 3));
                #pragma unroll
                for (int mt = 0; mt < 2; mt++)
                    #pragma unroll
                    for (int nh = 0; nh < 2; nh++)
                        #pragma unroll
                        for (int r = 0; r < 4; r++) {
                            float v = acc[mt][nh][r] + ((r & 1) ? e2v[nh].y : e2v[nh].x);
                            u32 col = (u32)(tile * 128 + wn * 16 + nh * 8 + 2 * (l & 3) + (r & 1));
                            track(b1[mt * 2 + (r >> 1)], b2[mt * 2 + (r >> 1)],
                                  ((u64)fkey(v) << 32) | col);
                            acc[mt][nh][r] = 0.f;
                        }
            }
            __syncthreads();
        }

        #pragma unroll
        for (int tr = 0; tr < 4; tr++)
            #pragma unroll
            for (int off = 1; off <= 2; off <<= 1) {
                u64 o1 = __shfl_xor_sync(0xffffffffu, b1[tr], off);
                u32 o2 = __shfl_xor_sync(0xffffffffu, b2[tr], off);
                u64 mx = (b1[tr] > o1) ? b1[tr] : o1;
                b1[tr] = (b1[tr] < o1) ? b1[tr] : o1;
                b2[tr] = min(min(b2[tr], o2), (u32)(mx >> 32));
            }
        u64* tab1 = (u64*)(smem + RS_B);
        u32* tab2 = (u32*)(smem + RS_B + 2048);
        if ((l & 3) == 0)
            #pragma unroll
            for (int tr = 0; tr < 4; tr++) {
                int row = (tr >> 1) * 16 + (tr & 1) * 8 + (l >> 2);
                tab1[row * 8 + wn] = b1[tr];
                tab2[row * 8 + wn] = b2[tr];
            }
        __syncthreads();
        if (tid < 32) {
            u64 best = ~0ull; u32 sec = 0xFFFFFFFFu;
            #pragma unroll
            for (int w = 0; w < 8; w++) {
                u64 p = tab1[tid * 8 + w];
                if (p < best) { sec = min(sec, (u32)(best >> 32)); best = p; }
                else          { sec = min(sec, (u32)(p >> 32)); }
                sec = min(sec, tab2[tid * 8 + w]);
            }
            int li = g * 32 + tid;
            if (li < cnt) {
                int n = g_flag_tok[li];
                float margin = fkeyinv(sec) - fkeyinv((u32)(best >> 32));
                if (margin > TAU2) g_idx[n] = (int)(best & 0xFFFFFFFFull);
                else {
                    int pp = atomicAdd(&g_flag2_cnt, 1);
                    g_flag2_tok[pp] = n;
                    g_best2[pp] = ~0ull;
                }
            }
        }
        __syncthreads();
    }
}

// ---------------- level 3: exact fp32, parallel over (token, 128-code chunk) ----------------
__global__ void __launch_bounds__(256) k_rescue_exact(const float* __restrict__ x,
                                                      const float* __restrict__ embed) {
    __shared__ float xs[256];
    __shared__ float part[256];
    __shared__ u64 red[128];
    int tid = threadIdx.x;
    int cnt = *((volatile int*)&g_flag2_cnt);
    int code = blockIdx.y * 128 + (tid & 127);
    int half = tid >> 7;
    for (int i = blockIdx.x; i < cnt; i += gridDim.x) {
        int n = g_flag2_tok[i];
        int b = n >> 12, s = n & 4095;
        xs[tid] = x[(size_t)b * 1048576u + (size_t)tid * 4096u + s];
        __syncthreads();
        const float4* e4 = (const float4*)(embed + code * 256) + half * 32;
        const float* xsp = xs + half * 128;
        float acc = 0.f;
        #pragma unroll 8
        for (int q = 0; q < 32; q++) {
            float4 ev = e4[q];
            acc = fmaf(ev.x, xsp[q*4+0], acc);
            acc = fmaf(ev.y, xsp[q*4+1], acc);
            acc = fmaf(ev.z, xsp[q*4+2], acc);
            acc = fmaf(ev.w, xsp[q*4+3], acc);
        }
        part[tid] = acc;
        __syncthreads();
        if (tid < 128) {
            float sc = g_e2[code] - 2.f * (part[tid] + part[tid + 128]);
            red[tid] = ((u64)fkey(sc) << 32) | (u32)code;
        }
        __syncthreads();
        for (int o = 64; o; o >>= 1) {
            if (tid < o) red[tid] = min(red[tid], red[tid + o]);
            __syncthreads();
        }
        if (tid == 0) atomicMin(&g_best2[i], red[0]);
        __syncthreads();
    }
}

__global__ void k_rescue_fin() {
    int cnt = *((volatile int*)&g_flag2_cnt);
    for (int i = threadIdx.x; i < cnt; i += blockDim.x)
        g_idx[g_flag2_tok[i]] = (int)(g_best2[i] & 0xFFFFFFFFull);
}

// ---------------- fused quantized write + loss + dw scatter + idx out ----------------
__global__ void k_quant_dw(const float* __restrict__ x,
                           const float* __restrict__ embed,
                           float* __restrict__ qout, float* __restrict__ idxf_out)
{
    int d0 = blockIdx.x << 3;
    int n  = (blockIdx.y << 8) + threadIdx.x;
    int b = n >> 12, s = n & 4095;
    size_t base = (size_t)b * 1048576u + s;
    int k = g_idx[n];
    float4 q0 = *(const float4*)(embed + k * D_DIM + d0);
    float4 q1 = *(const float4*)(embed + k * D_DIM + d0 + 4);
    if (blockIdx.x == 0) { idxf_out[n] = (float)k; atomicAdd(&g_batch_cs[k], 1.0f); }

    float xv[8], qv[8] = {q0.x, q0.y, q0.z, q0.w, q1.x, q1.y, q1.z, q1.w};
    #pragma unroll
    for (int i = 0; i < 8; i++) xv[i] = x[base + (size_t)(d0 + i) * 4096u];
    float ls = 0.f;
    #pragma unroll
    for (int i = 0; i < 8; i++) {
        float t = qv[i] - xv[i];
        qout[base + (size_t)(d0 + i) * 4096u] = xv[i] + t;
        ls = fmaf(t, t, ls);
    }

    float* dst = g_dw + k * D_DIM + d0;
    asm volatile("red.global.add.v4.f32 [%0], {%1,%2,%3,%4};"
                 :: "l"(dst), "f"(xv[0]), "f"(xv[1]), "f"(xv[2]), "f"(xv[3]) : "memory");
    asm volatile("red.global.add.v4.f32 [%0], {%1,%2,%3,%4};"
                 :: "l"(dst + 4), "f"(xv[4]), "f"(xv[5]), "f"(xv[6]), "f"(xv[7]) : "memory");

    #pragma unroll
    for (int o = 16; o; o >>= 1) ls += __shfl_down_sync(0xffffffffu, ls, o);
    __shared__ float ws[8];
    int tid = threadIdx.x;
    if ((tid & 31) == 0) ws[tid >> 5] = ls;
    __syncthreads();
    if (tid == 0) {
        float sum = 0.f;
        #pragma unroll
        for (int i = 0; i < 8; i++) sum += ws[i];
        g_partials[blockIdx.y * 32 + blockIdx.x] = sum;
    }
}

// ---------------- merged finalize: cs + new_embed + loss ----------------
__global__ void __launch_bounds__(256) k_fin2(const float* __restrict__ cluster_size,
                                              const float* __restrict__ embed_avg,
                                              float* __restrict__ loss_out,
                                              float* __restrict__ out_e)
{
    __shared__ float sb[256];
    int k = blockIdx.x, t = threadIdx.x;
    float part = 0.f;
    #pragma unroll
    for (int i = 0; i < 4; i++) {
        int c = t + i * 256;
        part += cluster_size[c] * 0.99f + 0.01f * g_batch_cs[c];
    }
    sb[t] = part; __syncthreads();
    for (int o = 128; o; o >>= 1) { if (t < o) sb[t] += sb[t + o]; __syncthreads(); }
    float nsum = sb[0];
    float ncs = cluster_size[k] * 0.99f + 0.01f * g_batch_cs[k];
    float cs = nsum * (ncs + 1e-5f) / (nsum + 1024.0f * 1e-5f);
    int o_ = k * D_DIM + t;
    out_e[o_] = (embed_avg[o_] * 0.99f + 0.01f * g_dw[o_]) / cs;

    if (k == 0) {
        __syncthreads();
        float s = 0.f;
        for (int i = t; i < 32 * 128; i += 256) s += g_partials[i];
        sb[t] = s; __syncthreads();
        for (int o = 128; o; o >>= 1) { if (t < o) sb[t] += sb[t + o]; __syncthreads(); }
        if (t == 0) loss_out[0] = 0.25f * sb[0] / (float)Q_ELEMS;
    }
}

// ---------------- launch ----------------
extern "C" void kernel_launch(void* const* d_in, const int* in_sizes, int n_in,
                              void* d_out, int out_size)
{
    const float* x         = (const float*)d_in[0];
    const float* embed     = (const float*)d_in[1];
    const float* embed_avg = (const float*)d_in[2];
    const float* cluster   = (const float*)d_in[3];

    float* out     = (float*)d_out;
    float* out_q   = out + 1;
    float* out_idx = out_q + Q_ELEMS;
    float* out_e   = out_idx + N_TOK;

    void *p_dw, *p_bc, *p_fc, *p_f2;
    cudaGetSymbolAddress(&p_dw, g_dw);
    cudaGetSymbolAddress(&p_bc, g_batch_cs);
    cudaGetSymbolAddress(&p_fc, g_flag_cnt);
    cudaGetSymbolAddress(&p_f2, g_flag2_cnt);
    cudaMemsetAsync(p_dw, 0, sizeof(float) * K_CODES * D_DIM, 0);
    cudaMemsetAsync(p_bc, 0, sizeof(float) * K_CODES, 0);
    cudaMemsetAsync(p_fc, 0, sizeof(int), 0);
    cudaMemsetAsync(p_f2, 0, sizeof(int), 0);

    cudaFuncSetAttribute(k_argmin,   cudaFuncAttributeMaxDynamicSharedMemorySize, SM_TOTAL);
    cudaFuncSetAttribute(k_rescue_t, cudaFuncAttributeMaxDynamicSharedMemorySize, RS_TOTAL);

    k_esplit<<<K_CODES, D_DIM>>>(embed);
    k_argmin<<<256, 256, SM_TOTAL>>>(x);
    k_rescue_t<<<192, 256, RS_TOTAL>>>(x);
    dim3 ge(128, 8);
    k_rescue_exact<<<ge, 256>>>(x, embed);
    k_rescue_fin<<<1, 256>>>();
    dim3 g(32, 128);
    k_quant_dw<<<g, 256>>>(x, embed, out_q, out_idx);
    k_fin2<<<K_CODES, D_DIM>>>(cluster, embed_avg, out, out_e);
}

// round 15
// speedup vs baseline: 1.2385x; 1.0429x over previous
#include <cuda_runtime.h>
#include <cuda_bf16.h>
#include <stdint.h>

typedef unsigned u32; typedef unsigned long long u64;

#define K_CODES 1024
#define D_DIM   256
#define N_TOK   32768
#define Q_ELEMS (8u*256u*4096u)
#define TAU     0.75f
#define TAU2    0.003f

#define XPITCH  264        /* x smem row pitch in bf16 elements (528 B) */
#define BPITCH  144        /* e tile row pitch in bytes (128 data + 16) */
#define SM_BT   18432      /* one 128-code x 64-d bf16 tile             */

/* main kernel smem map */
#define SM_XH   0
#define SM_B    67584
#define SM_TOTAL (67584 + 2 * SM_BT)          /* 104448 */

/* tensor-rescue smem map: 32 tokens/CTA */
#define RS_XH   0
#define RS_XL   16896
#define RS_B    33792
#define RS_TOTAL (33792 + 4 * SM_BT)          /* 107520 */

// ---------------- device scratch ----------------
__device__ __align__(16) __nv_bfloat16 g_Ebf[2][K_CODES][D_DIM];  // hi/lo of -2*embed
__device__ float g_e2[K_CODES];
__device__ int   g_idx[N_TOK];
__device__ float g_batch_cs[K_CODES];
__device__ float g_dw[K_CODES * D_DIM];
__device__ float g_partials[32 * 128];
__device__ int   g_flag_cnt;
__device__ int   g_flag_tok[N_TOK];
__device__ int   g_flag2_cnt;
__device__ int   g_flag2_tok[N_TOK];
__device__ u64   g_best2[N_TOK];

// ---------------- helpers ----------------
__device__ __forceinline__ u32 smem_u32(const void* p) {
    u32 a; asm("{ .reg .u64 t; cvta.to.shared.u64 t, %1; cvt.u32.u64 %0, t; }" : "=r"(a) : "l"(p)); return a;
}
__device__ __forceinline__ u32 fkey(float v) {
    u32 u = __float_as_uint(v); return (u & 0x80000000u) ? ~u : (u | 0x80000000u);
}
__device__ __forceinline__ float fkeyinv(u32 k) {
    u32 u = (k & 0x80000000u) ? (k & 0x7FFFFFFFu) : ~k; return __uint_as_float(u);
}
__device__ __forceinline__ void cpa16(u32 dst, const void* src) {
    asm volatile("cp.async.cg.shared.global [%0], [%1], 16;" :: "r"(dst), "l"(src));
}
#define CP_COMMIT() asm volatile("cp.async.commit_group;" ::: "memory")
#define CP_WAIT1()  asm volatile("cp.async.wait_group 1;" ::: "memory")
#define CP_WAIT0()  asm volatile("cp.async.wait_group 0;" ::: "memory")

__device__ __forceinline__ void ldm4(u32& r0, u32& r1, u32& r2, u32& r3, u32 a) {
    asm volatile("ldmatrix.sync.aligned.m8n8.x4.shared.b16 {%0,%1,%2,%3}, [%4];"
                 : "=r"(r0), "=r"(r1), "=r"(r2), "=r"(r3) : "r"(a));
}
__device__ __forceinline__ void mma16816(float* c, const u32* a, const u32* b) {
    asm volatile("mma.sync.aligned.m16n8k16.row.col.f32.bf16.bf16.f32 "
                 "{%0,%1,%2,%3}, {%4,%5,%6,%7}, {%8,%9}, {%0,%1,%2,%3};"
                 : "+f"(c[0]), "+f"(c[1]), "+f"(c[2]), "+f"(c[3])
                 : "r"(a[0]), "r"(a[1]), "r"(a[2]), "r"(a[3]), "r"(b[0]), "r"(b[1]));
}
__device__ __forceinline__ void track(u64& b1, u32& b2, u64 pk) {
    if (pk < b1) { b2 = min(b2, (u32)(b1 >> 32)); b1 = pk; }
    else         { b2 = min(b2, (u32)(pk >> 32)); }
}

// ---------------- prep: bf16 hi/lo of -2*embed + e2 + scratch zeroing ----------------
__global__ void k_esplit(const float* __restrict__ embed) {
    int k = blockIdx.x, d = threadIdx.x;
    // fold former memsets into this kernel (runs before every consumer each replay)
    g_dw[k * D_DIM + d] = 0.f;
    if (d == 0) g_batch_cs[k] = 0.f;
    if (k == 0 && d == 0) { g_flag_cnt = 0; g_flag2_cnt = 0; }

    float e = embed[k * D_DIM + d];
    float v = -2.0f * e;
    __nv_bfloat16 h = __float2bfloat16(v);
    g_Ebf[0][k][d] = h;
    g_Ebf[1][k][d] = __float2bfloat16(v - __bfloat162float(h));
    float s = e * e;
    #pragma unroll
    for (int o = 16; o; o >>= 1) s += __shfl_down_sync(0xffffffffu, s, o);
    __shared__ float ws[8];
    if ((d & 31) == 0) ws[d >> 5] = s;
    __syncthreads();
    if (d == 0) {
        float t = 0.f;
        #pragma unroll
        for (int i = 0; i < 8; i++) t += ws[i];
        g_e2[k] = t;
    }
}

// ---------------- level 1: single-pass xh*eh GEMM over all tokens ----------------
__global__ void __launch_bounds__(256, 2) k_argmin(const float* __restrict__ x) {
    extern __shared__ __align__(128) char smem[];
    u32 smb = smem_u32(smem);
    const int tid = threadIdx.x, l = tid & 31, wid = tid >> 5;
    const int wm = wid & 3, wn = wid >> 2;
    const int m0 = blockIdx.x * 128;
    const int b = m0 >> 12, s0 = m0 & 4095;

    __nv_bfloat16* xh = (__nv_bfloat16*)(smem + SM_XH);
    {   // fill x tile (hi only): [128 tok][256 d]
        int tok = tid & 127, dh = tid >> 7;
        const float* xp = x + (size_t)b * 1048576u + s0 + tok;
        #pragma unroll 4
        for (int i = 0; i < 128; i++) {
            int d = dh + 2 * i;
            xh[tok * XPITCH + d] = __float2bfloat16(xp[(size_t)d * 4096u]);
        }
    }

    auto prefetch = [&](int step) {
        int tile = step >> 2, chunk = step & 3;
        u32 dst = smb + SM_B + (u32)(step & 1) * SM_BT;
        const char* src0 = (const char*)&g_Ebf[0][tile * 128][0] + chunk * 128;
        #pragma unroll
        for (int i = 0; i < 4; i++) {
            int idx = tid + i * 256;
            int crow = idx >> 3, seg = idx & 7;
            cpa16(dst + crow * BPITCH + seg * 16, src0 + (size_t)crow * 512 + seg * 16);
        }
        CP_COMMIT();
    };

    float acc[2][8][4];
    u64 b1[4]; u32 b2[4];
    #pragma unroll
    for (int q = 0; q < 4; q++) { b1[q] = ~0ull; b2[q] = 0xFFFFFFFFu; }
    #pragma unroll
    for (int mt = 0; mt < 2; mt++)
        #pragma unroll
        for (int nt = 0; nt < 8; nt++)
            #pragma unroll
            for (int r = 0; r < 4; r++) acc[mt][nt][r] = 0.f;

    __syncthreads();
    prefetch(0);

    const u32 aoff = (u32)((l & 7) + ((l >> 3) & 1) * 8) * 528 + ((l >> 4) & 1) * 16;
    const u32 boff = (u32)((l & 7) + ((l >> 4) & 1) * 8) * BPITCH + ((l >> 3) & 1) * 16;

    for (int step = 0; step < 32; step++) {
        int tile = step >> 2, chunk = step & 3;
        if (step < 31) { prefetch(step + 1); CP_WAIT1(); } else { CP_WAIT0(); }
        __syncthreads();
        u32 Bb = smb + SM_B + (u32)(step & 1) * SM_BT;
        #pragma unroll
        for (int ks = 0; ks < 4; ks++) {
            u32 kbyte = (u32)chunk * 128 + ks * 32;
            u32 ah[2][4];
            #pragma unroll
            for (int mt = 0; mt < 2; mt++)
                ldm4(ah[mt][0], ah[mt][1], ah[mt][2], ah[mt][3],
                     smb + SM_XH + (u32)(wm * 32 + mt * 16) * 528 + kbyte + aoff);
            u32 bb[4][4];
            #pragma unroll
            for (int ng = 0; ng < 4; ng++)
                ldm4(bb[ng][0], bb[ng][1], bb[ng][2], bb[ng][3],
                     Bb + (u32)(wn * 64 + ng * 16) * BPITCH + ks * 32 + boff);
            #pragma unroll
            for (int mt = 0; mt < 2; mt++)
                #pragma unroll
                for (int ng = 0; ng < 4; ng++) {
                    mma16816(acc[mt][ng * 2],     ah[mt], &bb[ng][0]);
                    mma16816(acc[mt][ng * 2 + 1], ah[mt], &bb[ng][2]);
                }
        }
        if (chunk == 3) {
            float2 e2v[8];
            #pragma unroll
            for (int nt = 0; nt < 8; nt++)
                e2v[nt] = *(const float2*)(g_e2 + tile * 128 + wn * 64 + nt * 8 + 2 * (l & 3));
            #pragma unroll
            for (int mt = 0; mt < 2; mt++)
                #pragma unroll
                for (int nt = 0; nt < 8; nt++)
                    #pragma unroll
                    for (int r = 0; r < 4; r++) {
                        float v = acc[mt][nt][r] + ((r & 1) ? e2v[nt].y : e2v[nt].x);
                        u32 col = (u32)(tile * 128 + wn * 64 + nt * 8 + 2 * (l & 3) + (r & 1));
                        track(b1[mt * 2 + (r >> 1)], b2[mt * 2 + (r >> 1)],
                              ((u64)fkey(v) << 32) | col);
                        acc[mt][nt][r] = 0.f;
                    }
        }
        __syncthreads();
    }

    // merge lanes (l&3) sharing each row
    #pragma unroll
    for (int tr = 0; tr < 4; tr++)
        #pragma unroll
        for (int off = 1; off <= 2; off <<= 1) {
            u64 o1 = __shfl_xor_sync(0xffffffffu, b1[tr], off);
            u32 o2 = __shfl_xor_sync(0xffffffffu, b2[tr], off);
            u64 mx = (b1[tr] > o1) ? b1[tr] : o1;
            b1[tr] = (b1[tr] < o1) ? b1[tr] : o1;
            b2[tr] = min(min(b2[tr], o2), (u32)(mx >> 32));
        }
    u64* tab1 = (u64*)(smem + SM_B);
    u32* tab2 = (u32*)(smem + SM_B + 2048);
    if ((l & 3) == 0)
        #pragma unroll
        for (int tr = 0; tr < 4; tr++) {
            int row = wm * 32 + (tr >> 1) * 16 + (tr & 1) * 8 + (l >> 2);
            tab1[row * 2 + wn] = b1[tr];
            tab2[row * 2 + wn] = b2[tr];
        }
    __syncthreads();
    if (tid < 128) {
        u64 p = tab1[tid * 2], q = tab1[tid * 2 + 1];
        u64 best = p < q ? p : q, worse = p < q ? q : p;
        u32 sec = min(min(tab2[tid * 2], tab2[tid * 2 + 1]), (u32)(worse >> 32));
        int n = m0 + tid;
        g_idx[n] = (int)(best & 0xFFFFFFFFull);
        float margin = fkeyinv(sec) - fkeyinv((u32)(best >> 32));
        if (!(margin > TAU)) { int pp = atomicAdd(&g_flag_cnt, 1); g_flag_tok[pp] = n; }
    }
}

// ---------------- level 2: 3-pass tensor rescue, 32 flagged tokens / CTA ----------------
__global__ void __launch_bounds__(256, 2) k_rescue_t(const float* __restrict__ x) {
    extern __shared__ __align__(128) char smem[];
    u32 smb = smem_u32(smem);
    const int tid = threadIdx.x, l = tid & 31, wn = tid >> 5;   // 8 warps, 16 codes each
    int cnt = *((volatile int*)&g_flag_cnt);
    int G = (cnt + 31) >> 5;

    const u32 aoff = (u32)((l & 7) + ((l >> 3) & 1) * 8) * 528 + ((l >> 4) & 1) * 16;
    const u32 boff = (u32)((l & 7) + ((l >> 4) & 1) * 8) * BPITCH + ((l >> 3) & 1) * 16;
    __nv_bfloat16* xh = (__nv_bfloat16*)(smem + RS_XH);
    __nv_bfloat16* xl = (__nv_bfloat16*)(smem + RS_XL);

    for (int g = blockIdx.x; g < G; g += gridDim.x) {
        {   // gather 32 flagged tokens into smem hi/lo
            int slot = tid >> 3, seg = tid & 7;
            int li = g * 32 + slot;
            int n = g_flag_tok[li < cnt ? li : cnt - 1];
            int b = n >> 12, s = n & 4095;
            const float* xp = x + (size_t)b * 1048576u + s;
            #pragma unroll 4
            for (int i = 0; i < 32; i++) {
                int d = seg * 32 + i;
                float v = xp[(size_t)d * 4096u];
                __nv_bfloat16 h = __float2bfloat16(v);
                xh[slot * XPITCH + d] = h;
                xl[slot * XPITCH + d] = __float2bfloat16(v - __bfloat162float(h));
            }
        }

        auto prefetch = [&](int step) {
            int tile = step >> 2, chunk = step & 3;
            u32 dstb = smb + RS_B + (u32)(step & 1) * (2 * SM_BT);
            #pragma unroll
            for (int op = 0; op < 2; op++) {
                const char* src0 = (const char*)&g_Ebf[op][tile * 128][0] + chunk * 128;
                u32 dst = dstb + op * SM_BT;
                #pragma unroll
                for (int i = 0; i < 4; i++) {
                    int idx = tid + i * 256;
                    int crow = idx >> 3, seg = idx & 7;
                    cpa16(dst + crow * BPITCH + seg * 16, src0 + (size_t)crow * 512 + seg * 16);
                }
            }
            CP_COMMIT();
        };

        float acc[2][2][4];
        u64 b1[4]; u32 b2[4];
        #pragma unroll
        for (int q = 0; q < 4; q++) { b1[q] = ~0ull; b2[q] = 0xFFFFFFFFu; }
        #pragma unroll
        for (int mt = 0; mt < 2; mt++)
            #pragma unroll
            for (int nh = 0; nh < 2; nh++)
                #pragma unroll
                for (int r = 0; r < 4; r++) acc[mt][nh][r] = 0.f;

        __syncthreads();
        prefetch(0);

        for (int step = 0; step < 32; step++) {
            int tile = step >> 2, chunk = step & 3;
            if (step < 31) { prefetch(step + 1); CP_WAIT1(); } else { CP_WAIT0(); }
            __syncthreads();
            u32 Bb = smb + RS_B + (u32)(step & 1) * (2 * SM_BT);
            #pragma unroll
            for (int ks = 0; ks < 4; ks++) {
                u32 kbyte = (u32)chunk * 128 + ks * 32;
                u32 ah[2][4], al[2][4], bh[4], bl[4];
                #pragma unroll
                for (int mt = 0; mt < 2; mt++) {
                    u32 rowb = (u32)(mt * 16) * 528 + kbyte + aoff;
                    ldm4(ah[mt][0], ah[mt][1], ah[mt][2], ah[mt][3], smb + RS_XH + rowb);
                    ldm4(al[mt][0], al[mt][1], al[mt][2], al[mt][3], smb + RS_XL + rowb);
                }
                u32 brow = (u32)(wn * 16) * BPITCH + ks * 32 + boff;
                ldm4(bh[0], bh[1], bh[2], bh[3], Bb + brow);
                ldm4(bl[0], bl[1], bl[2], bl[3], Bb + SM_BT + brow);
                #pragma unroll
                for (int mt = 0; mt < 2; mt++) {
                    mma16816(acc[mt][0], ah[mt], &bh[0]);
                    mma16816(acc[mt][1], ah[mt], &bh[2]);
                    mma16816(acc[mt][0], ah[mt], &bl[0]);
                    mma16816(acc[mt][1], ah[mt], &bl[2]);
                    mma16816(acc[mt][0], al[mt], &bh[0]);
                    mma16816(acc[mt][1], al[mt], &bh[2]);
                }
            }
            if (chunk == 3) {
                float2 e2v[2];
                #pragma unroll
                for (int nh = 0; nh < 2; nh++)
                    e2v[nh] = *(const float2*)(g_e2 + tile * 128 + wn * 16 + nh * 8 + 2 * (l & 3));
                #pragma unroll
                for (int mt = 0; mt < 2; mt++)
                    #pragma unroll
                    for (int nh = 0; nh < 2; nh++)
                        #pragma unroll
                        for (int r = 0; r < 4; r++) {
                            float v = acc[mt][nh][r] + ((r & 1) ? e2v[nh].y : e2v[nh].x);
                            u32 col = (u32)(tile * 128 + wn * 16 + nh * 8 + 2 * (l & 3) + (r & 1));
                            track(b1[mt * 2 + (r >> 1)], b2[mt * 2 + (r >> 1)],
                                  ((u64)fkey(v) << 32) | col);
                            acc[mt][nh][r] = 0.f;
                        }
            }
            __syncthreads();
        }

        #pragma unroll
        for (int tr = 0; tr < 4; tr++)
            #pragma unroll
            for (int off = 1; off <= 2; off <<= 1) {
                u64 o1 = __shfl_xor_sync(0xffffffffu, b1[tr], off);
                u32 o2 = __shfl_xor_sync(0xffffffffu, b2[tr], off);
                u64 mx = (b1[tr] > o1) ? b1[tr] : o1;
                b1[tr] = (b1[tr] < o1) ? b1[tr] : o1;
                b2[tr] = min(min(b2[tr], o2), (u32)(mx >> 32));
            }
        u64* tab1 = (u64*)(smem + RS_B);
        u32* tab2 = (u32*)(smem + RS_B + 2048);
        if ((l & 3) == 0)
            #pragma unroll
            for (int tr = 0; tr < 4; tr++) {
                int row = (tr >> 1) * 16 + (tr & 1) * 8 + (l >> 2);
                tab1[row * 8 + wn] = b1[tr];
                tab2[row * 8 + wn] = b2[tr];
            }
        __syncthreads();
        if (tid < 32) {
            u64 best = ~0ull; u32 sec = 0xFFFFFFFFu;
            #pragma unroll
            for (int w = 0; w < 8; w++) {
                u64 p = tab1[tid * 8 + w];
                if (p < best) { sec = min(sec, (u32)(best >> 32)); best = p; }
                else          { sec = min(sec, (u32)(p >> 32)); }
                sec = min(sec, tab2[tid * 8 + w]);
            }
            int li = g * 32 + tid;
            if (li < cnt) {
                int n = g_flag_tok[li];
                float margin = fkeyinv(sec) - fkeyinv((u32)(best >> 32));
                if (margin > TAU2) g_idx[n] = (int)(best & 0xFFFFFFFFull);
                else {
                    int pp = atomicAdd(&g_flag2_cnt, 1);
                    g_flag2_tok[pp] = n;
                    g_best2[pp] = ~0ull;
                }
            }
        }
        __syncthreads();
    }
}

// ---------------- level 3: exact fp32, parallel over (token, 128-code chunk) ----------------
__global__ void __launch_bounds__(256) k_rescue_exact(const float* __restrict__ x,
                                                      const float* __restrict__ embed) {
    __shared__ float xs[256];
    __shared__ float part[256];
    __shared__ u64 red[128];
    int tid = threadIdx.x;
    int cnt = *((volatile int*)&g_flag2_cnt);
    int code = blockIdx.y * 128 + (tid & 127);
    int half = tid >> 7;
    for (int i = blockIdx.x; i < cnt; i += gridDim.x) {
        int n = g_flag2_tok[i];
        int b = n >> 12, s = n & 4095;
        xs[tid] = x[(size_t)b * 1048576u + (size_t)tid * 4096u + s];
        __syncthreads();
        const float4* e4 = (const float4*)(embed + code * 256) + half * 32;
        const float* xsp = xs + half * 128;
        float acc = 0.f;
        #pragma unroll 8
        for (int q = 0; q < 32; q++) {
            float4 ev = e4[q];
            acc = fmaf(ev.x, xsp[q*4+0], acc);
            acc = fmaf(ev.y, xsp[q*4+1], acc);
            acc = fmaf(ev.z, xsp[q*4+2], acc);
            acc = fmaf(ev.w, xsp[q*4+3], acc);
        }
        part[tid] = acc;
        __syncthreads();
        if (tid < 128) {
            float sc = g_e2[code] - 2.f * (part[tid] + part[tid + 128]);
            red[tid] = ((u64)fkey(sc) << 32) | (u32)code;
        }
        __syncthreads();
        for (int o = 64; o; o >>= 1) {
            if (tid < o) red[tid] = min(red[tid], red[tid + o]);
            __syncthreads();
        }
        if (tid == 0) atomicMin(&g_best2[i], red[0]);
        __syncthreads();
    }
}

__global__ void k_rescue_fin() {
    int cnt = *((volatile int*)&g_flag2_cnt);
    for (int i = threadIdx.x; i < cnt; i += blockDim.x)
        g_idx[g_flag2_tok[i]] = (int)(g_best2[i] & 0xFFFFFFFFull);
}

// ---------------- fused quantized write + loss + dw scatter + idx out ----------------
__global__ void k_quant_dw(const float* __restrict__ x,
                           const float* __restrict__ embed,
                           float* __restrict__ qout, float* __restrict__ idxf_out)
{
    int d0 = blockIdx.x << 3;
    int n  = (blockIdx.y << 8) + threadIdx.x;
    int b = n >> 12, s = n & 4095;
    size_t base = (size_t)b * 1048576u + s;
    int k = g_idx[n];
    float4 q0 = *(const float4*)(embed + k * D_DIM + d0);
    float4 q1 = *(const float4*)(embed + k * D_DIM + d0 + 4);
    if (blockIdx.x == 0) { idxf_out[n] = (float)k; atomicAdd(&g_batch_cs[k], 1.0f); }

    float xv[8], qv[8] = {q0.x, q0.y, q0.z, q0.w, q1.x, q1.y, q1.z, q1.w};
    #pragma unroll
    for (int i = 0; i < 8; i++) xv[i] = x[base + (size_t)(d0 + i) * 4096u];
    float ls = 0.f;
    #pragma unroll
    for (int i = 0; i < 8; i++) {
        float t = qv[i] - xv[i];
        qout[base + (size_t)(d0 + i) * 4096u] = xv[i] + t;
        ls = fmaf(t, t, ls);
    }

    float* dst = g_dw + k * D_DIM + d0;
    asm volatile("red.global.add.v4.f32 [%0], {%1,%2,%3,%4};"
                 :: "l"(dst), "f"(xv[0]), "f"(xv[1]), "f"(xv[2]), "f"(xv[3]) : "memory");
    asm volatile("red.global.add.v4.f32 [%0], {%1,%2,%3,%4};"
                 :: "l"(dst + 4), "f"(xv[4]), "f"(xv[5]), "f"(xv[6]), "f"(xv[7]) : "memory");

    #pragma unroll
    for (int o = 16; o; o >>= 1) ls += __shfl_down_sync(0xffffffffu, ls, o);
    __shared__ float ws[8];
    int tid = threadIdx.x;
    if ((tid & 31) == 0) ws[tid >> 5] = ls;
    __syncthreads();
    if (tid == 0) {
        float sum = 0.f;
        #pragma unroll
        for (int i = 0; i < 8; i++) sum += ws[i];
        g_partials[blockIdx.y * 32 + blockIdx.x] = sum;
    }
}

// ---------------- merged finalize: cs + new_embed + loss ----------------
__global__ void __launch_bounds__(256) k_fin2(const float* __restrict__ cluster_size,
                                              const float* __restrict__ embed_avg,
                                              float* __restrict__ loss_out,
                                              float* __restrict__ out_e)
{
    __shared__ float sb[256];
    int k = blockIdx.x, t = threadIdx.x;
    float part = 0.f;
    #pragma unroll
    for (int i = 0; i < 4; i++) {
        int c = t + i * 256;
        part += cluster_size[c] * 0.99f + 0.01f * g_batch_cs[c];
    }
    sb[t] = part; __syncthreads();
    for (int o = 128; o; o >>= 1) { if (t < o) sb[t] += sb[t + o]; __syncthreads(); }
    float nsum = sb[0];
    float ncs = cluster_size[k] * 0.99f + 0.01f * g_batch_cs[k];
    float cs = nsum * (ncs + 1e-5f) / (nsum + 1024.0f * 1e-5f);
    int o_ = k * D_DIM + t;
    out_e[o_] = (embed_avg[o_] * 0.99f + 0.01f * g_dw[o_]) / cs;

    if (k == 0) {
        __syncthreads();
        float s = 0.f;
        for (int i = t; i < 32 * 128; i += 256) s += g_partials[i];
        sb[t] = s; __syncthreads();
        for (int o = 128; o; o >>= 1) { if (t < o) sb[t] += sb[t + o]; __syncthreads(); }
        if (t == 0) loss_out[0] = 0.25f * sb[0] / (float)Q_ELEMS;
    }
}

// ---------------- launch ----------------
extern "C" void kernel_launch(void* const* d_in, const int* in_sizes, int n_in,
                              void* d_out, int out_size)
{
    const float* x         = (const float*)d_in[0];
    const float* embed     = (const float*)d_in[1];
    const float* embed_avg = (const float*)d_in[2];
    const float* cluster   = (const float*)d_in[3];

    float* out     = (float*)d_out;
    float* out_q   = out + 1;
    float* out_idx = out_q + Q_ELEMS;
    float* out_e   = out_idx + N_TOK;

    cudaFuncSetAttribute(k_argmin,   cudaFuncAttributeMaxDynamicSharedMemorySize, SM_TOTAL);
    cudaFuncSetAttribute(k_rescue_t, cudaFuncAttributeMaxDynamicSharedMemorySize, RS_TOTAL);

    k_esplit<<<K_CODES, D_DIM>>>(embed);
    k_argmin<<<256, 256, SM_TOTAL>>>(x);
    k_rescue_t<<<192, 256, RS_TOTAL>>>(x);
    dim3 ge(128, 8);
    k_rescue_exact<<<ge, 256>>>(x, embed);
    k_rescue_fin<<<1, 256>>>();
    dim3 g(32, 128);
    k_quant_dw<<<g, 256>>>(x, embed, out_q, out_idx);
    k_fin2<<<K_CODES, D_DIM>>>(cluster, embed_avg, out, out_e);
}